// round 11
// baseline (speedup 1.0000x reference)
#include <cuda_runtime.h>
#include <cuda_fp16.h>
#include <math.h>

// Problem constants
#define Bc   2
#define Tt   512
#define Nf   6
#define Dd   32
#define HIDc 128
#define NHc  4
#define HDc  32
#define Lc   3072      // Tt*Nf
#define GHc  32
#define FDc  128
#define EPSc 1e-5f

#define NCHUNK 6
#define CHUNK  512
#define SHIFT  8.0f    // uniform score shift (cancels exactly in O = sum o / sum su)

// Scratch (device globals: no allocation allowed)
__device__ __half d_Qh[Bc*NHc*Lc*HDc];   // fp16 Q (pre-scaled by 1/sqrt(HD)) [bh][l][d]
__device__ __half d_Kh[Bc*NHc*Lc*HDc];   // fp16 K [bh][l][d]
__device__ __half d_Vt[Bc*NHc*HDc*Lc];   // fp16 V transposed [bh][d][l]
__device__ float  d_SV[Bc*Tt*HIDc];      // suffix sums of V beyond block t
__device__ float  d_part[NCHUNK*Bc*Lc*HIDc]; // unnormalized attention partials
__device__ float  d_psum[NCHUNK*Bc*NHc*Lc];  // softmax denominator partials
__device__ float  d_SP[Bc*Tt*HIDc];      // pooled attention rows (pre o_w)

// D(16x8) += A(16x16,f16) * B(16x8,f16), fp32 accum.
__device__ __forceinline__ void mma_f16(float c[4],
    unsigned a0, unsigned a1, unsigned a2, unsigned a3,
    unsigned b0, unsigned b1)
{
    asm volatile(
        "mma.sync.aligned.m16n8k16.row.col.f32.f16.f16.f32 "
        "{%0,%1,%2,%3}, {%4,%5,%6,%7}, {%8,%9}, {%0,%1,%2,%3};"
        : "+f"(c[0]), "+f"(c[1]), "+f"(c[2]), "+f"(c[3])
        : "r"(a0), "r"(a1), "r"(a2), "r"(a3), "r"(b0), "r"(b1));
}

// ---------------------------------------------------------------------------
// Fused gater + gated QKV. One block (128 threads) per 8 tokens.
#define QTOK 8
__global__ __launch_bounds__(128) void qkv_gate_kernel(const float* __restrict__ x,
    const float* __restrict__ g_ln_w, const float* __restrict__ g_ln_b,
    const float* __restrict__ g_w1,   const float* __restrict__ g_b1,
    const float* __restrict__ g_w2,   const float* __restrict__ g_b2,
    const float* __restrict__ q_w,    const float* __restrict__ q_b,
    const float* __restrict__ k_w,    const float* __restrict__ k_b,
    const float* __restrict__ v_w,    const float* __restrict__ v_b)
{
    const float SC = 0.17677669529663688f;  // 1/sqrt(32)
    int t0 = blockIdx.x * QTOK;
    int tid = threadIdx.x;
    int w = tid >> 5, lane = tid & 31;

    __shared__ float xs[QTOK][32];
    __shared__ float xns[QTOK][32];
    __shared__ float gate[QTOK];

    #pragma unroll
    for (int i = tid; i < QTOK*32; i += 128)
        xs[i >> 5][i & 31] = x[(size_t)t0 * 32 + i];
    __syncthreads();

    // LayerNorm for gater input (warp w: tokens 2w, 2w+1)
    #pragma unroll
    for (int kk = 0; kk < 2; ++kk) {
        int t = w * 2 + kk;
        float xv = xs[t][lane];
        float s = xv, s2 = xv * xv;
        #pragma unroll
        for (int o = 16; o; o >>= 1) {
            s  += __shfl_xor_sync(0xffffffffu, s,  o);
            s2 += __shfl_xor_sync(0xffffffffu, s2, o);
        }
        float mu  = s * (1.0f / 32.0f);
        float var = s2 * (1.0f / 32.0f) - mu * mu;
        xns[t][lane] = (xv - mu) * rsqrtf(var + EPSc) * g_ln_w[lane] + g_ln_b[lane];
    }
    __syncthreads();

    // gater MLP (smem-broadcast matmul)
    #pragma unroll
    for (int kk = 0; kk < 2; ++kk) {
        int t = w * 2 + kk;
        float h = g_b1[lane];
        #pragma unroll
        for (int d = 0; d < 32; ++d)
            h += xns[t][d] * g_w1[d * GHc + lane];
        h = h / (1.0f + __expf(-h));
        float gp = h * g_w2[lane];
        #pragma unroll
        for (int o = 16; o; o >>= 1) gp += __shfl_xor_sync(0xffffffffu, gp, o);
        if (lane == 0) gate[t] = 1.0f / (1.0f + __expf(-(gp + g_b2[0])));
    }
    __syncthreads();

    int c = tid;
    float q[QTOK], k[QTOK], v[QTOK];
    float qb = q_b[c], kb = k_b[c], vb = v_b[c];
    #pragma unroll
    for (int t = 0; t < QTOK; ++t) { q[t] = qb; k[t] = kb; v[t] = vb; }
    #pragma unroll
    for (int dd = 0; dd < 32; ++dd) {
        float wq = q_w[dd * HIDc + c];
        float wk = k_w[dd * HIDc + c];
        float wv = v_w[dd * HIDc + c];
        #pragma unroll
        for (int t = 0; t < QTOK; ++t) {
            float xd = xs[t][dd];
            q[t] += xd * wq; k[t] += xd * wk; v[t] += xd * wv;
        }
    }

    int hh = c >> 5, d2 = c & 31;
    int b = t0 / Lc, lbase = t0 - b * Lc;
    int bh = b * NHc + hh;

    union { __half h[8]; uint4 u; } vp;
    #pragma unroll
    for (int t = 0; t < QTOK; ++t) {
        float g = gate[t];
        size_t idx = ((size_t)bh * Lc + lbase + t) * HDc + d2;
        d_Qh[idx] = __float2half_rn(q[t] * g * SC);
        d_Kh[idx] = __float2half_rn(k[t] * g);
        vp.h[t]   = __float2half_rn(v[t] * g);
    }
    *(uint4*)&d_Vt[((size_t)bh * HDc + d2) * Lc + lbase] = vp.u;
}

// ---------------------------------------------------------------------------
// Suffix sums of V over time blocks (warp-shuffle scan, 1 block barrier).
// grid = Bc*HIDc blocks, block = 512 threads.
__global__ void scan_sv_kernel() {
    int col = blockIdx.x;
    int b = col >> 7, c = col & 127;
    int h = c >> 5, d = c & 31;
    int t = threadIdx.x;
    int wid = t >> 5, lane = t & 31;
    __shared__ float wsum[16];

    const __half* vp = d_Vt + ((size_t)(b * NHc + h) * HDc + d) * Lc;
    float val = 0.0f;
    #pragma unroll
    for (int k = 0; k < Nf; ++k) val += __half2float(vp[t * Nf + k]);

    // inclusive suffix within warp: s(lane) = sum val[lane..31]
    float s = val;
    #pragma unroll
    for (int off = 1; off < 32; off <<= 1) {
        float o = __shfl_down_sync(0xffffffffu, s, off);
        if (lane + off < 32) s += o;
    }
    if (lane == 0) wsum[wid] = s;   // warp total
    __syncthreads();
    float later = 0.0f;
    #pragma unroll
    for (int ww = 0; ww < 16; ++ww)
        if (ww > wid) later += wsum[ww];
    d_SV[((size_t)b * Tt + t) * HIDc + c] = (s - val) + later;  // exclusive suffix
}

// ---------------------------------------------------------------------------
// Tensor-core block-causal attention: fp16 scoring + fp16 PV (fp32 accum),
// split-K over 512-key chunks (additive partials; p=exp(s-8), shift cancels).
// 128 threads, 4 warps x 16 queries = 64 queries/CTA, 32-key tiles,
// ping-pong double-buffered K/V smem (ONE barrier per tile).
#define TQ3 64
#define TK3 32
#define KSTH 40  // K smem row stride (halves)
#define VSTR 40  // V^T smem row stride (halves)
#define PSTR 40  // psh row stride (halves)
__global__ __launch_bounds__(128, 6) void attn_kernel()
{
    // map blockIdx.x -> (qtile bx, key chunk)
    int id = blockIdx.x;
    int bx = 0, l0, emax;
    for (;;) {
        l0 = Lc - TQ3 * (bx + 1);
        emax = 6 * ((l0 + TQ3 - 1) / 6) + 6;
        int nch = (emax + CHUNK - 1) / CHUNK;
        if (id < nch) break;
        id -= nch; ++bx;
    }
    int chunk = id;
    int h  = blockIdx.y;
    int b  = blockIdx.z;
    int bh = b * NHc + h;

    const __half* Qb = d_Qh + (size_t)bh * Lc * HDc;
    const __half* Kb = d_Kh + (size_t)bh * Lc * HDc;
    const __half* Vt = d_Vt + (size_t)bh * HDc * Lc;
    float* partp = d_part + (size_t)chunk * (Bc*Lc*HIDc);

    __shared__ __align__(16) __half Ksh[2][TK3 * KSTH];   // [buf][key][dim]
    __shared__ __align__(16) __half Vsh[2][HDc * VSTR];   // [buf][dim(32)][key(32)]
    __shared__ __align__(16) __half psh[TQ3 * PSTR];      // [query][key] fp16

    int tid  = threadIdx.x;
    int w    = tid >> 5;
    int lane = tid & 31;
    int g    = lane >> 2;        // groupID
    int tig  = lane & 3;         // thread-in-group
    int qbase = w * 16;

    // Q A-fragments (fp16, k16 steps s=0,1), held in registers
    unsigned qa[2][4];
    const __half* Qp = Qb + (size_t)(l0 + qbase) * 32;
    #pragma unroll
    for (int s = 0; s < 2; ++s) {
        qa[s][0] = *(const unsigned*)(Qp + (size_t)g * 32 + 16*s + 2*tig);
        qa[s][1] = *(const unsigned*)(Qp + (size_t)(g + 8) * 32 + 16*s + 2*tig);
        qa[s][2] = *(const unsigned*)(Qp + (size_t)g * 32 + 16*s + 2*tig + 8);
        qa[s][3] = *(const unsigned*)(Qp + (size_t)(g + 8) * 32 + 16*s + 2*tig + 8);
    }

    int endA = 6 * ((l0 + qbase + g) / 6) + 6;        // causal end, row g
    int endB = 6 * ((l0 + qbase + g + 8) / 6) + 6;    // causal end, row g+8
    int wend = 6 * ((l0 + qbase + 15) / 6) + 6;       // warp's max end

    int kstart = chunk * CHUNK;
    int kend   = min(emax, kstart + CHUNK);           // CTA's chunk range

    float o[2][2][4] = {};       // O^T accum [md][nq][reg]
    float su_lo = 0.f, su_hi = 0.f;

    // tile loader mapping: 128 thr -> 32 rows x 8 halves each
    int trow = tid >> 2;
    int tcol = (tid & 3) * 8;

    // preload tile 0 into buffer 0
    {
        uint4 k0 = *(const uint4*)(Kb + (size_t)(kstart + trow) * 32 + tcol);
        uint4 v0 = *(const uint4*)(Vt + (size_t)trow * Lc + kstart + tcol);
        *(uint4*)(Ksh[0] + trow * KSTH + tcol) = k0;
        *(uint4*)(Vsh[0] + trow * VSTR + tcol) = v0;
    }
    __syncthreads();

    int cur = 0;
    for (int kb = kstart; kb < kend; kb += TK3, cur ^= 1) {
        // store NEXT tile into the other buffer (overlaps compute on cur)
        if (kb + TK3 < kend) {
            uint4 kN = *(const uint4*)(Kb + (size_t)(kb + TK3 + trow) * 32 + tcol);
            uint4 vN = *(const uint4*)(Vt + (size_t)trow * Lc + kb + TK3 + tcol);
            *(uint4*)(Ksh[cur ^ 1] + trow * KSTH + tcol) = kN;
            *(uint4*)(Vsh[cur ^ 1] + trow * VSTR + tcol) = vN;
        }

        if (kb < wend) {
            // ---- scoring: S(16q x 32k) = Q * K^T via fp16 mma ----
            #pragma unroll
            for (int j = 0; j < 4; ++j) {
                float c[4] = {0.f, 0.f, 0.f, 0.f};
                const __half* kr = Ksh[cur] + (8*j + g) * KSTH;
                #pragma unroll
                for (int s = 0; s < 2; ++s) {
                    unsigned b0 = *(const unsigned*)(kr + 16*s + 2*tig);
                    unsigned b1 = *(const unsigned*)(kr + 16*s + 2*tig + 8);
                    mma_f16(c, qa[s][0], qa[s][1], qa[s][2], qa[s][3], b0, b1);
                }
                int ke = kb + 8*j + 2*tig;
                float p0 = (ke     < endA) ? __expf(c[0] - SHIFT) : 0.f;
                float p1 = (ke + 1 < endA) ? __expf(c[1] - SHIFT) : 0.f;
                float p2 = (ke     < endB) ? __expf(c[2] - SHIFT) : 0.f;
                float p3 = (ke + 1 < endB) ? __expf(c[3] - SHIFT) : 0.f;
                __half2 hA = __floats2half2_rn(p0, p1);
                __half2 hB = __floats2half2_rn(p2, p3);
                float2 fA = __half22float2(hA);
                float2 fB = __half22float2(hB);
                su_lo += fA.x + fA.y;
                su_hi += fB.x + fB.y;
                *(__half2*)(psh + (qbase + g) * PSTR + 8*j + 2*tig)     = hA;
                *(__half2*)(psh + (qbase + g + 8) * PSTR + 8*j + 2*tig) = hB;
            }
            __syncwarp();

            // ---- PV: O^T(32d x 16q) += V^T * P^T via fp16 mma ----
            #pragma unroll
            for (int s = 0; s < 2; ++s) {
                unsigned pb00 = *(const unsigned*)(psh + (qbase + g) * PSTR + 16*s + 2*tig);
                unsigned pb01 = *(const unsigned*)(psh + (qbase + g) * PSTR + 16*s + 2*tig + 8);
                unsigned pb10 = *(const unsigned*)(psh + (qbase + 8 + g) * PSTR + 16*s + 2*tig);
                unsigned pb11 = *(const unsigned*)(psh + (qbase + 8 + g) * PSTR + 16*s + 2*tig + 8);
                #pragma unroll
                for (int md = 0; md < 2; ++md) {
                    const __half* v0 = Vsh[cur] + (16*md + g) * VSTR;
                    const __half* v1 = Vsh[cur] + (16*md + g + 8) * VSTR;
                    unsigned a0 = *(const unsigned*)(v0 + 16*s + 2*tig);
                    unsigned a1 = *(const unsigned*)(v1 + 16*s + 2*tig);
                    unsigned a2 = *(const unsigned*)(v0 + 16*s + 2*tig + 8);
                    unsigned a3 = *(const unsigned*)(v1 + 16*s + 2*tig + 8);
                    mma_f16(o[md][0], a0, a1, a2, a3, pb00, pb01);
                    mma_f16(o[md][1], a0, a1, a2, a3, pb10, pb11);
                }
            }
        }
        __syncthreads();   // next buffer fully stored; cur buffer free for reuse
    }

    // reduce denominator partials within each quad (over tig)
    su_lo += __shfl_xor_sync(0xffffffffu, su_lo, 1);
    su_lo += __shfl_xor_sync(0xffffffffu, su_lo, 2);
    su_hi += __shfl_xor_sync(0xffffffffu, su_hi, 1);
    su_hi += __shfl_xor_sync(0xffffffffu, su_hi, 2);
    if (tig == 0) {
        size_t sb = (size_t)chunk * (Bc*NHc*Lc) + (size_t)bh * Lc + l0 + qbase;
        d_psum[sb + g]     = su_lo;
        d_psum[sb + g + 8] = su_hi;
    }

    #pragma unroll
    for (int md = 0; md < 2; ++md) {
        #pragma unroll
        for (int nq = 0; nq < 2; ++nq) {
            int qloc = qbase + 8*nq + 2*tig;
            size_t base = ((size_t)b * Lc + l0 + qloc) * HIDc + h * HDc + 16*md + g;
            partp[base]            = o[md][nq][0];
            partp[base + HIDc]     = o[md][nq][1];
            partp[base + 8]        = o[md][nq][2];
            partp[base + HIDc + 8] = o[md][nq][3];
        }
    }
}

// ---------------------------------------------------------------------------
// Combine split-K partials + pool(6) + exact 1e-9 masked tail -> d_SP.
// grid = Bc*Tt blocks x 128 threads; fully unrolled independent loads.
__global__ __launch_bounds__(128) void combine_kernel()
{
    int bt = blockIdx.x;
    int b = bt / Tt, tt = bt - b * Tt;
    int c = threadIdx.x;
    int h = c >> 5;

    int end = tt * Nf + Nf;
    int nc = (end + CHUNK - 1) / CHUNK;   // live chunks for this time block

    float p = 0.0f;
    #pragma unroll
    for (int k = 0; k < Nf; ++k) {
        int l = tt * Nf + k;
        float su = 0.f, oo = 0.f;
        #pragma unroll
        for (int cc = 0; cc < NCHUNK; ++cc) {
            if (cc < nc) {
                su += d_psum[(size_t)cc * (Bc*NHc*Lc) + ((size_t)b*NHc + h)*Lc + l];
                oo += d_part[(size_t)cc * (Bc*Lc*HIDc) + ((size_t)b*Lc + l)*HIDc + c];
            }
        }
        p += oo / su;
    }
    d_SP[(size_t)bt * HIDc + c] =
        p * (1.0f / Nf) + 1e-9f * d_SV[(size_t)bt * HIDc + c];
}

// ---------------------------------------------------------------------------
// o_w -> LN -> f_w -> SiLU on pooled rows.
// 2 rows per block, 512 blocks, 256 threads (dd reduction split in halves).
#define FTOK 2
__global__ __launch_bounds__(256) void final_kernel(
    const float* __restrict__ o_w,    const float* __restrict__ o_b,
    const float* __restrict__ f_ln_w, const float* __restrict__ f_ln_b,
    const float* __restrict__ f_w,    const float* __restrict__ f_b,
    float* __restrict__ out)
{
    int p0 = blockIdx.x * FTOK;
    int tid = threadIdx.x;
    int c = tid & 127;
    int half = tid >> 7;
    int w = c >> 5, lane = c & 31;
    int d0 = half * 64;

    __shared__ float sp[FTOK][128];
    __shared__ float pacc[2][FTOK][128];
    __shared__ float sln[FTOK][128];
    __shared__ float redA[FTOK][4], redB[FTOK][4];

    #pragma unroll
    for (int i = tid; i < FTOK * 128; i += 256)
        ((float*)sp)[i] = d_SP[(size_t)p0 * HIDc + i];
    __syncthreads();

    // ---- o_w matmul, dd split across halves ----
    float acc[FTOK] = {0.f, 0.f};
    #pragma unroll 8
    for (int dd = d0; dd < d0 + 64; ++dd) {
        float wv = o_w[dd * HIDc + c];
        #pragma unroll
        for (int t = 0; t < FTOK; ++t) acc[t] += sp[t][dd] * wv;
    }
    #pragma unroll
    for (int t = 0; t < FTOK; ++t) pacc[half][t][c] = acc[t];
    __syncthreads();

    float o[FTOK];
    #pragma unroll
    for (int t = 0; t < FTOK; ++t)
        o[t] = pacc[0][t][c] + pacc[1][t][c] + o_b[c];

    // ---- LayerNorm stats (half 0 only) ----
    if (half == 0) {
        #pragma unroll
        for (int t = 0; t < FTOK; ++t) {
            float s = o[t], s2 = o[t] * o[t];
            #pragma unroll
            for (int off = 16; off; off >>= 1) {
                s  += __shfl_xor_sync(0xffffffffu, s,  off);
                s2 += __shfl_xor_sync(0xffffffffu, s2, off);
            }
            if (lane == 0) { redA[t][w] = s; redB[t][w] = s2; }
        }
    }
    __syncthreads();
    if (half == 0) {
        #pragma unroll
        for (int t = 0; t < FTOK; ++t) {
            float S  = redA[t][0] + redA[t][1] + redA[t][2] + redA[t][3];
            float S2 = redB[t][0] + redB[t][1] + redB[t][2] + redB[t][3];
            float mu  = S * (1.0f / 128.0f);
            float var = S2 * (1.0f / 128.0f) - mu * mu;
            sln[t][c] = (o[t] - mu) * rsqrtf(var + EPSc) * f_ln_w[c] + f_ln_b[c];
        }
    }
    __syncthreads();

    // ---- f_w matmul, dd split across halves ----
    float f[FTOK] = {0.f, 0.f};
    #pragma unroll 8
    for (int dd = d0; dd < d0 + 64; ++dd) {
        float wv = f_w[dd * HIDc + c];
        #pragma unroll
        for (int t = 0; t < FTOK; ++t) f[t] += sln[t][dd] * wv;
    }
    #pragma unroll
    for (int t = 0; t < FTOK; ++t) pacc[half][t][c] = f[t];
    __syncthreads();

    if (half == 0) {
        #pragma unroll
        for (int t = 0; t < FTOK; ++t) {
            float ff = pacc[0][t][c] + pacc[1][t][c] + f_b[c];
            out[(size_t)(p0 + t) * FDc + c] = ff / (1.0f + __expf(-ff));
        }
    }
}

// ---------------------------------------------------------------------------
extern "C" void kernel_launch(void* const* d_in, const int* in_sizes, int n_in,
                              void* d_out, int out_size)
{
    const float* x      = (const float*)d_in[0];
    const float* g_ln_w = (const float*)d_in[1];
    const float* g_ln_b = (const float*)d_in[2];
    const float* g_w1   = (const float*)d_in[3];
    const float* g_b1   = (const float*)d_in[4];
    const float* g_w2   = (const float*)d_in[5];
    const float* g_b2   = (const float*)d_in[6];
    const float* q_w    = (const float*)d_in[7];
    const float* q_b    = (const float*)d_in[8];
    const float* k_w    = (const float*)d_in[9];
    const float* k_b    = (const float*)d_in[10];
    const float* v_w    = (const float*)d_in[11];
    const float* v_b    = (const float*)d_in[12];
    const float* o_w    = (const float*)d_in[13];
    const float* o_b    = (const float*)d_in[14];
    const float* f_ln_w = (const float*)d_in[15];
    const float* f_ln_b = (const float*)d_in[16];
    const float* f_w    = (const float*)d_in[17];
    const float* f_b    = (const float*)d_in[18];

    // exact CTA count for the (qtile, chunk) decomposition
    int total = 0;
    for (int bx = 0; bx < Lc / TQ3; ++bx) {
        int l0 = Lc - TQ3 * (bx + 1);
        int emax = 6 * ((l0 + TQ3 - 1) / 6) + 6;
        total += (emax + CHUNK - 1) / CHUNK;
    }

    qkv_gate_kernel<<<(Bc * Lc) / QTOK, 128>>>(x, g_ln_w, g_ln_b, g_w1, g_b1,
                                               g_w2, g_b2, q_w, q_b, k_w, k_b,
                                               v_w, v_b);
    scan_sv_kernel<<<Bc * HIDc, Tt>>>();
    attn_kernel<<<dim3(total, NHc, Bc), 128>>>();
    combine_kernel<<<Bc * Tt, 128>>>();
    final_kernel<<<(Bc * Tt) / FTOK, 256>>>(o_w, o_b, f_ln_w, f_ln_b, f_w, f_b,
                                            (float*)d_out);
}

// round 12
// speedup vs baseline: 1.0034x; 1.0034x over previous
#include <cuda_runtime.h>
#include <cuda_fp16.h>
#include <math.h>

// Problem constants
#define Bc   2
#define Tt   512
#define Nf   6
#define Dd   32
#define HIDc 128
#define NHc  4
#define HDc  32
#define Lc   3072      // Tt*Nf
#define GHc  32
#define FDc  128
#define EPSc 1e-5f

#define NCHUNK 6
#define CHUNK  512
#define SHIFT  8.0f    // uniform score shift (cancels exactly in O = sum o / sum su)

// Scratch (device globals: no allocation allowed)
__device__ __half d_Qh[Bc*NHc*Lc*HDc];   // fp16 Q (pre-scaled by 1/sqrt(HD)) [bh][l][d]
__device__ __half d_Kh[Bc*NHc*Lc*HDc];   // fp16 K [bh][l][d]
__device__ __half d_Vt[Bc*NHc*HDc*Lc];   // fp16 V transposed [bh][d][l]
__device__ float  d_SV[Bc*Tt*HIDc];      // suffix sums of V beyond block t
__device__ float  d_part[NCHUNK*Bc*Lc*HIDc]; // unnormalized attention partials
__device__ float  d_psum[NCHUNK*Bc*NHc*Lc];  // softmax denominator partials
__device__ float  d_SP[Bc*Tt*HIDc];      // pooled attention rows (pre o_w)

// D(16x8) += A(16x16,f16) * B(16x8,f16), fp32 accum.
__device__ __forceinline__ void mma_f16(float c[4],
    unsigned a0, unsigned a1, unsigned a2, unsigned a3,
    unsigned b0, unsigned b1)
{
    asm volatile(
        "mma.sync.aligned.m16n8k16.row.col.f32.f16.f16.f32 "
        "{%0,%1,%2,%3}, {%4,%5,%6,%7}, {%8,%9}, {%0,%1,%2,%3};"
        : "+f"(c[0]), "+f"(c[1]), "+f"(c[2]), "+f"(c[3])
        : "r"(a0), "r"(a1), "r"(a2), "r"(a3), "r"(b0), "r"(b1));
}

// ---------------------------------------------------------------------------
// Fused gater + gated QKV. One block (128 threads) per 8 tokens.
#define QTOK 8
__global__ __launch_bounds__(128) void qkv_gate_kernel(const float* __restrict__ x,
    const float* __restrict__ g_ln_w, const float* __restrict__ g_ln_b,
    const float* __restrict__ g_w1,   const float* __restrict__ g_b1,
    const float* __restrict__ g_w2,   const float* __restrict__ g_b2,
    const float* __restrict__ q_w,    const float* __restrict__ q_b,
    const float* __restrict__ k_w,    const float* __restrict__ k_b,
    const float* __restrict__ v_w,    const float* __restrict__ v_b)
{
    const float SC = 0.17677669529663688f;  // 1/sqrt(32)
    int t0 = blockIdx.x * QTOK;
    int tid = threadIdx.x;
    int w = tid >> 5, lane = tid & 31;

    __shared__ float xs[QTOK][32];
    __shared__ float xns[QTOK][32];
    __shared__ float gate[QTOK];

    #pragma unroll
    for (int i = tid; i < QTOK*32; i += 128)
        xs[i >> 5][i & 31] = x[(size_t)t0 * 32 + i];
    __syncthreads();

    // LayerNorm for gater input (warp w: tokens 2w, 2w+1)
    #pragma unroll
    for (int kk = 0; kk < 2; ++kk) {
        int t = w * 2 + kk;
        float xv = xs[t][lane];
        float s = xv, s2 = xv * xv;
        #pragma unroll
        for (int o = 16; o; o >>= 1) {
            s  += __shfl_xor_sync(0xffffffffu, s,  o);
            s2 += __shfl_xor_sync(0xffffffffu, s2, o);
        }
        float mu  = s * (1.0f / 32.0f);
        float var = s2 * (1.0f / 32.0f) - mu * mu;
        xns[t][lane] = (xv - mu) * rsqrtf(var + EPSc) * g_ln_w[lane] + g_ln_b[lane];
    }
    __syncthreads();

    // gater MLP (smem-broadcast matmul)
    #pragma unroll
    for (int kk = 0; kk < 2; ++kk) {
        int t = w * 2 + kk;
        float h = g_b1[lane];
        #pragma unroll
        for (int d = 0; d < 32; ++d)
            h += xns[t][d] * g_w1[d * GHc + lane];
        h = h / (1.0f + __expf(-h));
        float gp = h * g_w2[lane];
        #pragma unroll
        for (int o = 16; o; o >>= 1) gp += __shfl_xor_sync(0xffffffffu, gp, o);
        if (lane == 0) gate[t] = 1.0f / (1.0f + __expf(-(gp + g_b2[0])));
    }
    __syncthreads();

    int c = tid;
    float q[QTOK], k[QTOK], v[QTOK];
    float qb = q_b[c], kb = k_b[c], vb = v_b[c];
    #pragma unroll
    for (int t = 0; t < QTOK; ++t) { q[t] = qb; k[t] = kb; v[t] = vb; }
    #pragma unroll
    for (int dd = 0; dd < 32; ++dd) {
        float wq = q_w[dd * HIDc + c];
        float wk = k_w[dd * HIDc + c];
        float wv = v_w[dd * HIDc + c];
        #pragma unroll
        for (int t = 0; t < QTOK; ++t) {
            float xd = xs[t][dd];
            q[t] += xd * wq; k[t] += xd * wk; v[t] += xd * wv;
        }
    }

    int hh = c >> 5, d2 = c & 31;
    int b = t0 / Lc, lbase = t0 - b * Lc;
    int bh = b * NHc + hh;

    union { __half h[8]; uint4 u; } vp;
    #pragma unroll
    for (int t = 0; t < QTOK; ++t) {
        float g = gate[t];
        size_t idx = ((size_t)bh * Lc + lbase + t) * HDc + d2;
        d_Qh[idx] = __float2half_rn(q[t] * g * SC);
        d_Kh[idx] = __float2half_rn(k[t] * g);
        vp.h[t]   = __float2half_rn(v[t] * g);
    }
    *(uint4*)&d_Vt[((size_t)bh * HDc + d2) * Lc + lbase] = vp.u;
}

// ---------------------------------------------------------------------------
// Suffix sums of V over time blocks, computed directly from d_Vt.
// grid = Bc*HIDc blocks, block = 512 threads (Hillis-Steele).
__global__ void scan_sv_kernel() {
    int col = blockIdx.x;
    int b = col >> 7, c = col & 127;
    int h = c >> 5, d = c & 31;
    int t = threadIdx.x;
    __shared__ float sh[Tt];
    const __half* vp = d_Vt + ((size_t)(b * NHc + h) * HDc + d) * Lc;
    float val = 0.0f;
    #pragma unroll
    for (int k = 0; k < Nf; ++k) val += __half2float(vp[t * Nf + k]);
    sh[t] = val;
    __syncthreads();
    #pragma unroll
    for (int off = 1; off < Tt; off <<= 1) {
        float add = (t + off < Tt) ? sh[t + off] : 0.0f;
        __syncthreads();
        sh[t] += add;
        __syncthreads();
    }
    d_SV[((size_t)b * Tt + t) * HIDc + c] = sh[t] - val;   // exclusive suffix sum
}

// ---------------------------------------------------------------------------
// Tensor-core block-causal attention: fp16 scoring + fp16 PV (fp32 accum),
// split-K over 512-key chunks (additive partials; p=exp(s-8), shift cancels).
// 128 threads, 4 warps x 16 queries = 64 queries/CTA, 32-key tiles.
// Ping-pong smem with REGISTER prefetch: tile n+1 sits in registers (already
// arrived), is stored at loop top, then tile n+2 loads issue and overlap the
// compute on buf[cur]. ONE barrier per tile.
#define TQ3 64
#define TK3 32
#define KSTH 40  // K smem row stride (halves)
#define VSTR 40  // V^T smem row stride (halves)
#define PSTR 40  // psh row stride (halves)
__global__ __launch_bounds__(128, 7) void attn_kernel()
{
    // map blockIdx.x -> (qtile bx, key chunk)
    int id = blockIdx.x;
    int bx = 0, l0, emax;
    for (;;) {
        l0 = Lc - TQ3 * (bx + 1);
        emax = 6 * ((l0 + TQ3 - 1) / 6) + 6;
        int nch = (emax + CHUNK - 1) / CHUNK;
        if (id < nch) break;
        id -= nch; ++bx;
    }
    int chunk = id;
    int h  = blockIdx.y;
    int b  = blockIdx.z;
    int bh = b * NHc + h;

    const __half* Qb = d_Qh + (size_t)bh * Lc * HDc;
    const __half* Kb = d_Kh + (size_t)bh * Lc * HDc;
    const __half* Vt = d_Vt + (size_t)bh * HDc * Lc;
    float* partp = d_part + (size_t)chunk * (Bc*Lc*HIDc);

    __shared__ __align__(16) __half Ksh[2][TK3 * KSTH];   // [buf][key][dim]
    __shared__ __align__(16) __half Vsh[2][HDc * VSTR];   // [buf][dim(32)][key(32)]
    __shared__ __align__(16) __half psh[TQ3 * PSTR];      // [query][key] fp16

    int tid  = threadIdx.x;
    int w    = tid >> 5;
    int lane = tid & 31;
    int g    = lane >> 2;        // groupID
    int tig  = lane & 3;         // thread-in-group
    int qbase = w * 16;

    // Q A-fragments (fp16, k16 steps s=0,1), held in registers
    unsigned qa[2][4];
    const __half* Qp = Qb + (size_t)(l0 + qbase) * 32;
    #pragma unroll
    for (int s = 0; s < 2; ++s) {
        qa[s][0] = *(const unsigned*)(Qp + (size_t)g * 32 + 16*s + 2*tig);
        qa[s][1] = *(const unsigned*)(Qp + (size_t)(g + 8) * 32 + 16*s + 2*tig);
        qa[s][2] = *(const unsigned*)(Qp + (size_t)g * 32 + 16*s + 2*tig + 8);
        qa[s][3] = *(const unsigned*)(Qp + (size_t)(g + 8) * 32 + 16*s + 2*tig + 8);
    }

    int endA = 6 * ((l0 + qbase + g) / 6) + 6;        // causal end, row g
    int endB = 6 * ((l0 + qbase + g + 8) / 6) + 6;    // causal end, row g+8
    int wend = 6 * ((l0 + qbase + 15) / 6) + 6;       // warp's max end

    int kstart = chunk * CHUNK;
    int kend   = min(emax, kstart + CHUNK);           // CTA's chunk range

    float o[2][2][4] = {};       // O^T accum [md][nq][reg]
    float su_lo = 0.f, su_hi = 0.f;

    // tile loader mapping: 128 thr -> 32 rows x 8 halves each
    int trow = tid >> 2;
    int tcol = (tid & 3) * 8;

    // preload tile 0 directly to buf 0; load tile 1 into registers
    {
        uint4 k0 = *(const uint4*)(Kb + (size_t)(kstart + trow) * 32 + tcol);
        uint4 v0 = *(const uint4*)(Vt + (size_t)trow * Lc + kstart + tcol);
        *(uint4*)(Ksh[0] + trow * KSTH + tcol) = k0;
        *(uint4*)(Vsh[0] + trow * VSTR + tcol) = v0;
    }
    uint4 kR, vR;
    if (kstart + TK3 < kend) {
        kR = *(const uint4*)(Kb + (size_t)(kstart + TK3 + trow) * 32 + tcol);
        vR = *(const uint4*)(Vt + (size_t)trow * Lc + kstart + TK3 + tcol);
    }
    __syncthreads();

    int cur = 0;
    for (int kb = kstart; kb < kend; kb += TK3, cur ^= 1) {
        // store already-arrived tile n+1 regs into the other buffer,
        // then issue loads for tile n+2 (overlap compute below)
        if (kb + TK3 < kend) {
            *(uint4*)(Ksh[cur ^ 1] + trow * KSTH + tcol) = kR;
            *(uint4*)(Vsh[cur ^ 1] + trow * VSTR + tcol) = vR;
            if (kb + 2*TK3 < kend) {
                kR = *(const uint4*)(Kb + (size_t)(kb + 2*TK3 + trow) * 32 + tcol);
                vR = *(const uint4*)(Vt + (size_t)trow * Lc + kb + 2*TK3 + tcol);
            }
        }

        if (kb < wend) {
            // ---- scoring: S(16q x 32k) = Q * K^T via fp16 mma ----
            #pragma unroll
            for (int j = 0; j < 4; ++j) {
                float c[4] = {0.f, 0.f, 0.f, 0.f};
                const __half* kr = Ksh[cur] + (8*j + g) * KSTH;
                #pragma unroll
                for (int s = 0; s < 2; ++s) {
                    unsigned b0 = *(const unsigned*)(kr + 16*s + 2*tig);
                    unsigned b1 = *(const unsigned*)(kr + 16*s + 2*tig + 8);
                    mma_f16(c, qa[s][0], qa[s][1], qa[s][2], qa[s][3], b0, b1);
                }
                int ke = kb + 8*j + 2*tig;
                float p0 = (ke     < endA) ? __expf(c[0] - SHIFT) : 0.f;
                float p1 = (ke + 1 < endA) ? __expf(c[1] - SHIFT) : 0.f;
                float p2 = (ke     < endB) ? __expf(c[2] - SHIFT) : 0.f;
                float p3 = (ke + 1 < endB) ? __expf(c[3] - SHIFT) : 0.f;
                __half2 hA = __floats2half2_rn(p0, p1);
                __half2 hB = __floats2half2_rn(p2, p3);
                float2 fA = __half22float2(hA);
                float2 fB = __half22float2(hB);
                su_lo += fA.x + fA.y;
                su_hi += fB.x + fB.y;
                *(__half2*)(psh + (qbase + g) * PSTR + 8*j + 2*tig)     = hA;
                *(__half2*)(psh + (qbase + g + 8) * PSTR + 8*j + 2*tig) = hB;
            }
            __syncwarp();

            // ---- PV: O^T(32d x 16q) += V^T * P^T via fp16 mma ----
            #pragma unroll
            for (int s = 0; s < 2; ++s) {
                unsigned pb00 = *(const unsigned*)(psh + (qbase + g) * PSTR + 16*s + 2*tig);
                unsigned pb01 = *(const unsigned*)(psh + (qbase + g) * PSTR + 16*s + 2*tig + 8);
                unsigned pb10 = *(const unsigned*)(psh + (qbase + 8 + g) * PSTR + 16*s + 2*tig);
                unsigned pb11 = *(const unsigned*)(psh + (qbase + 8 + g) * PSTR + 16*s + 2*tig + 8);
                #pragma unroll
                for (int md = 0; md < 2; ++md) {
                    const __half* v0 = Vsh[cur] + (16*md + g) * VSTR;
                    const __half* v1 = Vsh[cur] + (16*md + g + 8) * VSTR;
                    unsigned a0 = *(const unsigned*)(v0 + 16*s + 2*tig);
                    unsigned a1 = *(const unsigned*)(v1 + 16*s + 2*tig);
                    unsigned a2 = *(const unsigned*)(v0 + 16*s + 2*tig + 8);
                    unsigned a3 = *(const unsigned*)(v1 + 16*s + 2*tig + 8);
                    mma_f16(o[md][0], a0, a1, a2, a3, pb00, pb01);
                    mma_f16(o[md][1], a0, a1, a2, a3, pb10, pb11);
                }
            }
        }
        __syncthreads();   // buf[cur^1] fully stored; buf[cur] free for reuse
    }

    // reduce denominator partials within each quad (over tig)
    su_lo += __shfl_xor_sync(0xffffffffu, su_lo, 1);
    su_lo += __shfl_xor_sync(0xffffffffu, su_lo, 2);
    su_hi += __shfl_xor_sync(0xffffffffu, su_hi, 1);
    su_hi += __shfl_xor_sync(0xffffffffu, su_hi, 2);
    if (tig == 0) {
        size_t sb = (size_t)chunk * (Bc*NHc*Lc) + (size_t)bh * Lc + l0 + qbase;
        d_psum[sb + g]     = su_lo;
        d_psum[sb + g + 8] = su_hi;
    }

    #pragma unroll
    for (int md = 0; md < 2; ++md) {
        #pragma unroll
        for (int nq = 0; nq < 2; ++nq) {
            int qloc = qbase + 8*nq + 2*tig;
            size_t base = ((size_t)b * Lc + l0 + qloc) * HIDc + h * HDc + 16*md + g;
            partp[base]            = o[md][nq][0];
            partp[base + HIDc]     = o[md][nq][1];
            partp[base + 8]        = o[md][nq][2];
            partp[base + HIDc + 8] = o[md][nq][3];
        }
    }
}

// ---------------------------------------------------------------------------
// Combine split-K partials + pool(6) + exact 1e-9 masked tail -> d_SP.
// grid = Bc*Tt blocks x 128 threads; fully unrolled independent loads.
__global__ __launch_bounds__(128) void combine_kernel()
{
    int bt = blockIdx.x;
    int b = bt / Tt, tt = bt - b * Tt;
    int c = threadIdx.x;
    int h = c >> 5;

    int end = tt * Nf + Nf;
    int nc = (end + CHUNK - 1) / CHUNK;   // live chunks for this time block

    float p = 0.0f;
    #pragma unroll
    for (int k = 0; k < Nf; ++k) {
        int l = tt * Nf + k;
        float su = 0.f, oo = 0.f;
        #pragma unroll
        for (int cc = 0; cc < NCHUNK; ++cc) {
            if (cc < nc) {
                su += d_psum[(size_t)cc * (Bc*NHc*Lc) + ((size_t)b*NHc + h)*Lc + l];
                oo += d_part[(size_t)cc * (Bc*Lc*HIDc) + ((size_t)b*Lc + l)*HIDc + c];
            }
        }
        p += oo / su;
    }
    d_SP[(size_t)bt * HIDc + c] =
        p * (1.0f / Nf) + 1e-9f * d_SV[(size_t)bt * HIDc + c];
}

// ---------------------------------------------------------------------------
// o_w -> LN -> f_w -> SiLU on pooled rows.
// 4 rows per block, 256 blocks, 256 threads: the dd (reduction) dimension is
// split across the two 128-thread halves; partials reduced through smem.
#define FTOK 4
__global__ __launch_bounds__(256) void final_kernel(
    const float* __restrict__ o_w,    const float* __restrict__ o_b,
    const float* __restrict__ f_ln_w, const float* __restrict__ f_ln_b,
    const float* __restrict__ f_w,    const float* __restrict__ f_b,
    float* __restrict__ out)
{
    int p0 = blockIdx.x * FTOK;
    int tid = threadIdx.x;
    int c = tid & 127;
    int half = tid >> 7;
    int w = c >> 5, lane = c & 31;
    int d0 = half * 64;

    __shared__ float sp[FTOK][128];
    __shared__ float pacc[2][FTOK][128];
    __shared__ float sln[FTOK][128];
    __shared__ float redA[FTOK][4], redB[FTOK][4];

    #pragma unroll
    for (int i = tid; i < FTOK * 128; i += 256)
        ((float*)sp)[i] = d_SP[(size_t)p0 * HIDc + i];
    __syncthreads();

    // ---- o_w matmul, dd split across halves ----
    float acc[FTOK] = {0.f, 0.f, 0.f, 0.f};
    #pragma unroll 8
    for (int dd = d0; dd < d0 + 64; ++dd) {
        float wv = o_w[dd * HIDc + c];
        #pragma unroll
        for (int t = 0; t < FTOK; ++t) acc[t] += sp[t][dd] * wv;
    }
    #pragma unroll
    for (int t = 0; t < FTOK; ++t) pacc[half][t][c] = acc[t];
    __syncthreads();

    float o[FTOK];
    #pragma unroll
    for (int t = 0; t < FTOK; ++t)
        o[t] = pacc[0][t][c] + pacc[1][t][c] + o_b[c];

    // ---- LayerNorm stats (half 0 only) ----
    if (half == 0) {
        #pragma unroll
        for (int t = 0; t < FTOK; ++t) {
            float s = o[t], s2 = o[t] * o[t];
            #pragma unroll
            for (int off = 16; off; off >>= 1) {
                s  += __shfl_xor_sync(0xffffffffu, s,  off);
                s2 += __shfl_xor_sync(0xffffffffu, s2, off);
            }
            if (lane == 0) { redA[t][w] = s; redB[t][w] = s2; }
        }
    }
    __syncthreads();
    if (half == 0) {
        #pragma unroll
        for (int t = 0; t < FTOK; ++t) {
            float S  = redA[t][0] + redA[t][1] + redA[t][2] + redA[t][3];
            float S2 = redB[t][0] + redB[t][1] + redB[t][2] + redB[t][3];
            float mu  = S * (1.0f / 128.0f);
            float var = S2 * (1.0f / 128.0f) - mu * mu;
            sln[t][c] = (o[t] - mu) * rsqrtf(var + EPSc) * f_ln_w[c] + f_ln_b[c];
        }
    }
    __syncthreads();

    // ---- f_w matmul, dd split across halves ----
    float f[FTOK] = {0.f, 0.f, 0.f, 0.f};
    #pragma unroll 8
    for (int dd = d0; dd < d0 + 64; ++dd) {
        float wv = f_w[dd * HIDc + c];
        #pragma unroll
        for (int t = 0; t < FTOK; ++t) f[t] += sln[t][dd] * wv;
    }
    #pragma unroll
    for (int t = 0; t < FTOK; ++t) pacc[half][t][c] = f[t];
    __syncthreads();

    if (half == 0) {
        #pragma unroll
        for (int t = 0; t < FTOK; ++t) {
            float ff = pacc[0][t][c] + pacc[1][t][c] + f_b[c];
            out[(size_t)(p0 + t) * FDc + c] = ff / (1.0f + __expf(-ff));
        }
    }
}

// ---------------------------------------------------------------------------
extern "C" void kernel_launch(void* const* d_in, const int* in_sizes, int n_in,
                              void* d_out, int out_size)
{
    const float* x      = (const float*)d_in[0];
    const float* g_ln_w = (const float*)d_in[1];
    const float* g_ln_b = (const float*)d_in[2];
    const float* g_w1   = (const float*)d_in[3];
    const float* g_b1   = (const float*)d_in[4];
    const float* g_w2   = (const float*)d_in[5];
    const float* g_b2   = (const float*)d_in[6];
    const float* q_w    = (const float*)d_in[7];
    const float* q_b    = (const float*)d_in[8];
    const float* k_w    = (const float*)d_in[9];
    const float* k_b    = (const float*)d_in[10];
    const float* v_w    = (const float*)d_in[11];
    const float* v_b    = (const float*)d_in[12];
    const float* o_w    = (const float*)d_in[13];
    const float* o_b    = (const float*)d_in[14];
    const float* f_ln_w = (const float*)d_in[15];
    const float* f_ln_b = (const float*)d_in[16];
    const float* f_w    = (const float*)d_in[17];
    const float* f_b    = (const float*)d_in[18];

    // exact CTA count for the (qtile, chunk) decomposition
    int total = 0;
    for (int bx = 0; bx < Lc / TQ3; ++bx) {
        int l0 = Lc - TQ3 * (bx + 1);
        int emax = 6 * ((l0 + TQ3 - 1) / 6) + 6;
        total += (emax + CHUNK - 1) / CHUNK;
    }

    qkv_gate_kernel<<<(Bc * Lc) / QTOK, 128>>>(x, g_ln_w, g_ln_b, g_w1, g_b1,
                                               g_w2, g_b2, q_w, q_b, k_w, k_b,
                                               v_w, v_b);
    scan_sv_kernel<<<Bc * HIDc, Tt>>>();
    attn_kernel<<<dim3(total, NHc, Bc), 128>>>();
    combine_kernel<<<Bc * Tt, 128>>>();
    final_kernel<<<(Bc * Tt) / FTOK, 256>>>(o_w, o_b, f_ln_w, f_ln_b, f_w, f_b,
                                            (float*)d_out);
}

// round 13
// speedup vs baseline: 1.1357x; 1.1318x over previous
#include <cuda_runtime.h>
#include <cuda_fp16.h>
#include <math.h>

// Problem constants
#define Bc   2
#define Tt   512
#define Nf   6
#define Dd   32
#define HIDc 128
#define NHc  4
#define HDc  32
#define Lc   3072      // Tt*Nf
#define GHc  32
#define FDc  128
#define EPSc 1e-5f

#define NCHUNK 6
#define CHUNK  512
#define SHIFT2 12.0f   // uniform log2-domain score shift (cancels in sum o / sum su)
#define LOG2E  1.4426950408889634f

// Scratch (device globals: no allocation allowed)
__device__ __half d_Qh[Bc*NHc*Lc*HDc];   // fp16 Q (pre-scaled by log2e/sqrt(HD)) [bh][l][d]
__device__ __half d_Kh[Bc*NHc*Lc*HDc];   // fp16 K [bh][l][d]
__device__ __half d_Vt[Bc*NHc*HDc*Lc];   // fp16 V transposed [bh][d][l]
__device__ float  d_SV[Bc*Tt*HIDc];      // suffix sums of V beyond block t
__device__ float  d_part[NCHUNK*Bc*Lc*HIDc]; // unnormalized attention partials
__device__ float  d_psum[NCHUNK*Bc*NHc*Lc];  // softmax denominator partials
__device__ float  d_SP[Bc*Tt*HIDc];      // pooled attention rows (pre o_w)

// D(16x8) += A(16x16,f16) * B(16x8,f16), fp32 accum.
__device__ __forceinline__ void mma_f16(float c[4],
    unsigned a0, unsigned a1, unsigned a2, unsigned a3,
    unsigned b0, unsigned b1)
{
    asm volatile(
        "mma.sync.aligned.m16n8k16.row.col.f32.f16.f16.f32 "
        "{%0,%1,%2,%3}, {%4,%5,%6,%7}, {%8,%9}, {%0,%1,%2,%3};"
        : "+f"(c[0]), "+f"(c[1]), "+f"(c[2]), "+f"(c[3])
        : "r"(a0), "r"(a1), "r"(a2), "r"(a3), "r"(b0), "r"(b1));
}

// packed fp16 2^x
__device__ __forceinline__ unsigned ex2_f16x2(float x0, float x1) {
    unsigned in, out;
    asm("cvt.rn.f16x2.f32 %0, %2, %1;" : "=r"(in) : "f"(x0), "f"(x1));
    asm("ex2.approx.f16x2 %0, %1;" : "=r"(out) : "r"(in));
    return out;
}

// ---------------------------------------------------------------------------
// Fused gater + gated QKV. One block (128 threads) per 8 tokens.
#define QTOK 8
__global__ __launch_bounds__(128) void qkv_gate_kernel(const float* __restrict__ x,
    const float* __restrict__ g_ln_w, const float* __restrict__ g_ln_b,
    const float* __restrict__ g_w1,   const float* __restrict__ g_b1,
    const float* __restrict__ g_w2,   const float* __restrict__ g_b2,
    const float* __restrict__ q_w,    const float* __restrict__ q_b,
    const float* __restrict__ k_w,    const float* __restrict__ k_b,
    const float* __restrict__ v_w,    const float* __restrict__ v_b)
{
    const float SC = 0.17677669529663688f * LOG2E;  // log2e/sqrt(32)
    int t0 = blockIdx.x * QTOK;
    int tid = threadIdx.x;
    int w = tid >> 5, lane = tid & 31;

    __shared__ float xs[QTOK][32];
    __shared__ float xns[QTOK][32];
    __shared__ float gate[QTOK];

    #pragma unroll
    for (int i = tid; i < QTOK*32; i += 128)
        xs[i >> 5][i & 31] = x[(size_t)t0 * 32 + i];
    __syncthreads();

    // LayerNorm for gater input (warp w: tokens 2w, 2w+1)
    #pragma unroll
    for (int kk = 0; kk < 2; ++kk) {
        int t = w * 2 + kk;
        float xv = xs[t][lane];
        float s = xv, s2 = xv * xv;
        #pragma unroll
        for (int o = 16; o; o >>= 1) {
            s  += __shfl_xor_sync(0xffffffffu, s,  o);
            s2 += __shfl_xor_sync(0xffffffffu, s2, o);
        }
        float mu  = s * (1.0f / 32.0f);
        float var = s2 * (1.0f / 32.0f) - mu * mu;
        xns[t][lane] = (xv - mu) * rsqrtf(var + EPSc) * g_ln_w[lane] + g_ln_b[lane];
    }
    __syncthreads();

    // gater MLP (smem-broadcast matmul)
    #pragma unroll
    for (int kk = 0; kk < 2; ++kk) {
        int t = w * 2 + kk;
        float h = g_b1[lane];
        #pragma unroll
        for (int d = 0; d < 32; ++d)
            h += xns[t][d] * g_w1[d * GHc + lane];
        h = h / (1.0f + __expf(-h));
        float gp = h * g_w2[lane];
        #pragma unroll
        for (int o = 16; o; o >>= 1) gp += __shfl_xor_sync(0xffffffffu, gp, o);
        if (lane == 0) gate[t] = 1.0f / (1.0f + __expf(-(gp + g_b2[0])));
    }
    __syncthreads();

    int c = tid;
    float q[QTOK], k[QTOK], v[QTOK];
    float qb = q_b[c], kb = k_b[c], vb = v_b[c];
    #pragma unroll
    for (int t = 0; t < QTOK; ++t) { q[t] = qb; k[t] = kb; v[t] = vb; }
    #pragma unroll
    for (int dd = 0; dd < 32; ++dd) {
        float wq = q_w[dd * HIDc + c];
        float wk = k_w[dd * HIDc + c];
        float wv = v_w[dd * HIDc + c];
        #pragma unroll
        for (int t = 0; t < QTOK; ++t) {
            float xd = xs[t][dd];
            q[t] += xd * wq; k[t] += xd * wk; v[t] += xd * wv;
        }
    }

    int hh = c >> 5, d2 = c & 31;
    int b = t0 / Lc, lbase = t0 - b * Lc;
    int bh = b * NHc + hh;

    union { __half h[8]; uint4 u; } vp;
    #pragma unroll
    for (int t = 0; t < QTOK; ++t) {
        float g = gate[t];
        size_t idx = ((size_t)bh * Lc + lbase + t) * HDc + d2;
        d_Qh[idx] = __float2half_rn(q[t] * g * SC);
        d_Kh[idx] = __float2half_rn(k[t] * g);
        vp.h[t]   = __float2half_rn(v[t] * g);
    }
    *(uint4*)&d_Vt[((size_t)bh * HDc + d2) * Lc + lbase] = vp.u;
}

// ---------------------------------------------------------------------------
// Suffix sums of V over time blocks, computed directly from d_Vt.
// grid = Bc*HIDc blocks, block = 512 threads (Hillis-Steele).
__global__ void scan_sv_kernel() {
    int col = blockIdx.x;
    int b = col >> 7, c = col & 127;
    int h = c >> 5, d = c & 31;
    int t = threadIdx.x;
    __shared__ float sh[Tt];
    const __half* vp = d_Vt + ((size_t)(b * NHc + h) * HDc + d) * Lc;
    float val = 0.0f;
    #pragma unroll
    for (int k = 0; k < Nf; ++k) val += __half2float(vp[t * Nf + k]);
    sh[t] = val;
    __syncthreads();
    #pragma unroll
    for (int off = 1; off < Tt; off <<= 1) {
        float add = (t + off < Tt) ? sh[t + off] : 0.0f;
        __syncthreads();
        sh[t] += add;
        __syncthreads();
    }
    d_SV[((size_t)b * Tt + t) * HIDc + c] = sh[t] - val;   // exclusive suffix sum
}

// ---------------------------------------------------------------------------
// Tensor-core block-causal attention: fp16 scoring + fp16 PV (fp32 accum),
// split-K over 512-key chunks; scores in log2 domain, p = 2^(s - 12) via
// ex2.approx.f16x2 (shift cancels in sum o / sum su).
// 128 threads, 4 warps x 16 queries = 64 queries/CTA, 32-key tiles.
#define TQ3 64
#define TK3 32
#define KSTH 40  // K smem row stride (halves)
#define VSTR 40  // V^T smem row stride (halves)
#define PSTR 40  // psh row stride (halves)
__global__ __launch_bounds__(128, 7) void attn_kernel()
{
    // map blockIdx.x -> (qtile bx, key chunk)
    int id = blockIdx.x;
    int bx = 0, l0, emax;
    for (;;) {
        l0 = Lc - TQ3 * (bx + 1);
        emax = 6 * ((l0 + TQ3 - 1) / 6) + 6;
        int nch = (emax + CHUNK - 1) / CHUNK;
        if (id < nch) break;
        id -= nch; ++bx;
    }
    int chunk = id;
    int h  = blockIdx.y;
    int b  = blockIdx.z;
    int bh = b * NHc + h;

    const __half* Qb = d_Qh + (size_t)bh * Lc * HDc;
    const __half* Kb = d_Kh + (size_t)bh * Lc * HDc;
    const __half* Vt = d_Vt + (size_t)bh * HDc * Lc;
    float* partp = d_part + (size_t)chunk * (Bc*Lc*HIDc);

    __shared__ __align__(16) __half Ksh[TK3 * KSTH];   // [key][dim]
    __shared__ __align__(16) __half Vsh[HDc * VSTR];   // [dim(32)][key(32)]
    __shared__ __align__(16) __half psh[TQ3 * PSTR];   // [query][key] fp16

    int tid  = threadIdx.x;
    int w    = tid >> 5;
    int lane = tid & 31;
    int g    = lane >> 2;        // groupID
    int tig  = lane & 3;         // thread-in-group
    int qbase = w * 16;

    // Q A-fragments (fp16, k16 steps s=0,1), held in registers
    unsigned qa[2][4];
    const __half* Qp = Qb + (size_t)(l0 + qbase) * 32;
    #pragma unroll
    for (int s = 0; s < 2; ++s) {
        qa[s][0] = *(const unsigned*)(Qp + (size_t)g * 32 + 16*s + 2*tig);
        qa[s][1] = *(const unsigned*)(Qp + (size_t)(g + 8) * 32 + 16*s + 2*tig);
        qa[s][2] = *(const unsigned*)(Qp + (size_t)g * 32 + 16*s + 2*tig + 8);
        qa[s][3] = *(const unsigned*)(Qp + (size_t)(g + 8) * 32 + 16*s + 2*tig + 8);
    }

    int endA = 6 * ((l0 + qbase + g) / 6) + 6;        // causal end, row g
    int endB = 6 * ((l0 + qbase + g + 8) / 6) + 6;    // causal end, row g+8
    int wend = 6 * ((l0 + qbase + 15) / 6) + 6;       // warp's max end

    int kstart = chunk * CHUNK;
    int kend   = min(emax, kstart + CHUNK);           // CTA's chunk range

    float o[2][2][4] = {};       // O^T accum [md][nq][reg]
    float su_lo = 0.f, su_hi = 0.f;

    // tile loader mapping: 128 thr -> 32 rows x 8 halves each
    int trow = tid >> 2;
    int tcol = (tid & 3) * 8;

    uint4 kA = *(const uint4*)(Kb + (size_t)(kstart + trow) * 32 + tcol);
    uint4 vA = *(const uint4*)(Vt + (size_t)trow * Lc + kstart + tcol);

    for (int kb = kstart; kb < kend; kb += TK3) {
        __syncthreads();
        *(uint4*)(Ksh + trow * KSTH + tcol) = kA;
        *(uint4*)(Vsh + trow * VSTR + tcol) = vA;
        if (kb + TK3 < kend) {
            kA = *(const uint4*)(Kb + (size_t)(kb + TK3 + trow) * 32 + tcol);
            vA = *(const uint4*)(Vt + (size_t)trow * Lc + kb + TK3 + tcol);
        }
        __syncthreads();
        if (kb >= wend) continue;   // this warp done; still hits barriers

        // ---- scoring: S(16q x 32k) = Q * K^T via fp16 mma, per 8-key tile j ----
        #pragma unroll
        for (int j = 0; j < 4; ++j) {
            float c[4] = {0.f, 0.f, 0.f, 0.f};
            const __half* kr = Ksh + (8*j + g) * KSTH;
            #pragma unroll
            for (int s = 0; s < 2; ++s) {
                unsigned b0 = *(const unsigned*)(kr + 16*s + 2*tig);
                unsigned b1 = *(const unsigned*)(kr + 16*s + 2*tig + 8);
                mma_f16(c, qa[s][0], qa[s][1], qa[s][2], qa[s][3], b0, b1);
            }
            int ke = kb + 8*j + 2*tig;
            // p = 2^(s - 12) in fp16 pairs; causal mask by zeroing fp16 lanes
            unsigned pA = ex2_f16x2(c[0] - SHIFT2, c[1] - SHIFT2);
            unsigned pB = ex2_f16x2(c[2] - SHIFT2, c[3] - SHIFT2);
            unsigned mA = (ke < endA ? 0xFFFFu : 0u) | (ke + 1 < endA ? 0xFFFF0000u : 0u);
            unsigned mB = (ke < endB ? 0xFFFFu : 0u) | (ke + 1 < endB ? 0xFFFF0000u : 0u);
            pA &= mA;
            pB &= mB;
            float2 fA = __half22float2(*(__half2*)&pA);
            float2 fB = __half22float2(*(__half2*)&pB);
            su_lo += fA.x + fA.y;
            su_hi += fB.x + fB.y;
            *(unsigned*)(psh + (qbase + g) * PSTR + 8*j + 2*tig)     = pA;
            *(unsigned*)(psh + (qbase + g + 8) * PSTR + 8*j + 2*tig) = pB;
        }
        __syncwarp();

        // ---- PV: O^T(32d x 16q) += V^T * P^T via fp16 mma ----
        #pragma unroll
        for (int s = 0; s < 2; ++s) {
            unsigned pb00 = *(const unsigned*)(psh + (qbase + g) * PSTR + 16*s + 2*tig);
            unsigned pb01 = *(const unsigned*)(psh + (qbase + g) * PSTR + 16*s + 2*tig + 8);
            unsigned pb10 = *(const unsigned*)(psh + (qbase + 8 + g) * PSTR + 16*s + 2*tig);
            unsigned pb11 = *(const unsigned*)(psh + (qbase + 8 + g) * PSTR + 16*s + 2*tig + 8);
            #pragma unroll
            for (int md = 0; md < 2; ++md) {
                const __half* v0 = Vsh + (16*md + g) * VSTR;
                const __half* v1 = Vsh + (16*md + g + 8) * VSTR;
                unsigned a0 = *(const unsigned*)(v0 + 16*s + 2*tig);
                unsigned a1 = *(const unsigned*)(v1 + 16*s + 2*tig);
                unsigned a2 = *(const unsigned*)(v0 + 16*s + 2*tig + 8);
                unsigned a3 = *(const unsigned*)(v1 + 16*s + 2*tig + 8);
                mma_f16(o[md][0], a0, a1, a2, a3, pb00, pb01);
                mma_f16(o[md][1], a0, a1, a2, a3, pb10, pb11);
            }
        }
        __syncwarp();
    }

    // reduce denominator partials within each quad (over tig)
    su_lo += __shfl_xor_sync(0xffffffffu, su_lo, 1);
    su_lo += __shfl_xor_sync(0xffffffffu, su_lo, 2);
    su_hi += __shfl_xor_sync(0xffffffffu, su_hi, 1);
    su_hi += __shfl_xor_sync(0xffffffffu, su_hi, 2);
    if (tig == 0) {
        size_t sb = (size_t)chunk * (Bc*NHc*Lc) + (size_t)bh * Lc + l0 + qbase;
        d_psum[sb + g]     = su_lo;
        d_psum[sb + g + 8] = su_hi;
    }

    #pragma unroll
    for (int md = 0; md < 2; ++md) {
        #pragma unroll
        for (int nq = 0; nq < 2; ++nq) {
            int qloc = qbase + 8*nq + 2*tig;
            size_t base = ((size_t)b * Lc + l0 + qloc) * HIDc + h * HDc + 16*md + g;
            partp[base]            = o[md][nq][0];
            partp[base + HIDc]     = o[md][nq][1];
            partp[base + 8]        = o[md][nq][2];
            partp[base + HIDc + 8] = o[md][nq][3];
        }
    }
}

// ---------------------------------------------------------------------------
// Combine split-K partials + pool(6) + exact 1e-9 masked tail -> d_SP.
// grid = Bc*Tt blocks x 128 threads; fully unrolled independent loads.
__global__ __launch_bounds__(128) void combine_kernel()
{
    int bt = blockIdx.x;
    int b = bt / Tt, tt = bt - b * Tt;
    int c = threadIdx.x;
    int h = c >> 5;

    int end = tt * Nf + Nf;
    int nc = (end + CHUNK - 1) / CHUNK;   // live chunks for this time block

    float p = 0.0f;
    #pragma unroll
    for (int k = 0; k < Nf; ++k) {
        int l = tt * Nf + k;
        float su = 0.f, oo = 0.f;
        #pragma unroll
        for (int cc = 0; cc < NCHUNK; ++cc) {
            if (cc < nc) {
                su += d_psum[(size_t)cc * (Bc*NHc*Lc) + ((size_t)b*NHc + h)*Lc + l];
                oo += d_part[(size_t)cc * (Bc*Lc*HIDc) + ((size_t)b*Lc + l)*HIDc + c];
            }
        }
        p += oo / su;
    }
    d_SP[(size_t)bt * HIDc + c] =
        p * (1.0f / Nf) + 1e-9f * d_SV[(size_t)bt * HIDc + c];
}

// ---------------------------------------------------------------------------
// o_w -> LN -> f_w -> SiLU on pooled rows.
// 4 rows per block, 256 blocks, 256 threads: the dd (reduction) dimension is
// split across the two 128-thread halves; partials reduced through smem.
#define FTOK 4
__global__ __launch_bounds__(256) void final_kernel(
    const float* __restrict__ o_w,    const float* __restrict__ o_b,
    const float* __restrict__ f_ln_w, const float* __restrict__ f_ln_b,
    const float* __restrict__ f_w,    const float* __restrict__ f_b,
    float* __restrict__ out)
{
    int p0 = blockIdx.x * FTOK;
    int tid = threadIdx.x;
    int c = tid & 127;
    int half = tid >> 7;
    int w = c >> 5, lane = c & 31;
    int d0 = half * 64;

    __shared__ float sp[FTOK][128];
    __shared__ float pacc[2][FTOK][128];
    __shared__ float sln[FTOK][128];
    __shared__ float redA[FTOK][4], redB[FTOK][4];

    #pragma unroll
    for (int i = tid; i < FTOK * 128; i += 256)
        ((float*)sp)[i] = d_SP[(size_t)p0 * HIDc + i];
    __syncthreads();

    // ---- o_w matmul, dd split across halves ----
    float acc[FTOK] = {0.f, 0.f, 0.f, 0.f};
    #pragma unroll 8
    for (int dd = d0; dd < d0 + 64; ++dd) {
        float wv = o_w[dd * HIDc + c];
        #pragma unroll
        for (int t = 0; t < FTOK; ++t) acc[t] += sp[t][dd] * wv;
    }
    #pragma unroll
    for (int t = 0; t < FTOK; ++t) pacc[half][t][c] = acc[t];
    __syncthreads();

    float o[FTOK];
    #pragma unroll
    for (int t = 0; t < FTOK; ++t)
        o[t] = pacc[0][t][c] + pacc[1][t][c] + o_b[c];

    // ---- LayerNorm stats (half 0 only) ----
    if (half == 0) {
        #pragma unroll
        for (int t = 0; t < FTOK; ++t) {
            float s = o[t], s2 = o[t] * o[t];
            #pragma unroll
            for (int off = 16; off; off >>= 1) {
                s  += __shfl_xor_sync(0xffffffffu, s,  off);
                s2 += __shfl_xor_sync(0xffffffffu, s2, off);
            }
            if (lane == 0) { redA[t][w] = s; redB[t][w] = s2; }
        }
    }
    __syncthreads();
    if (half == 0) {
        #pragma unroll
        for (int t = 0; t < FTOK; ++t) {
            float S  = redA[t][0] + redA[t][1] + redA[t][2] + redA[t][3];
            float S2 = redB[t][0] + redB[t][1] + redB[t][2] + redB[t][3];
            float mu  = S * (1.0f / 128.0f);
            float var = S2 * (1.0f / 128.0f) - mu * mu;
            sln[t][c] = (o[t] - mu) * rsqrtf(var + EPSc) * f_ln_w[c] + f_ln_b[c];
        }
    }
    __syncthreads();

    // ---- f_w matmul, dd split across halves ----
    float f[FTOK] = {0.f, 0.f, 0.f, 0.f};
    #pragma unroll 8
    for (int dd = d0; dd < d0 + 64; ++dd) {
        float wv = f_w[dd * HIDc + c];
        #pragma unroll
        for (int t = 0; t < FTOK; ++t) f[t] += sln[t][dd] * wv;
    }
    #pragma unroll
    for (int t = 0; t < FTOK; ++t) pacc[half][t][c] = f[t];
    __syncthreads();

    if (half == 0) {
        #pragma unroll
        for (int t = 0; t < FTOK; ++t) {
            float ff = pacc[0][t][c] + pacc[1][t][c] + f_b[c];
            out[(size_t)(p0 + t) * FDc + c] = ff / (1.0f + __expf(-ff));
        }
    }
}

// ---------------------------------------------------------------------------
extern "C" void kernel_launch(void* const* d_in, const int* in_sizes, int n_in,
                              void* d_out, int out_size)
{
    const float* x      = (const float*)d_in[0];
    const float* g_ln_w = (const float*)d_in[1];
    const float* g_ln_b = (const float*)d_in[2];
    const float* g_w1   = (const float*)d_in[3];
    const float* g_b1   = (const float*)d_in[4];
    const float* g_w2   = (const float*)d_in[5];
    const float* g_b2   = (const float*)d_in[6];
    const float* q_w    = (const float*)d_in[7];
    const float* q_b    = (const float*)d_in[8];
    const float* k_w    = (const float*)d_in[9];
    const float* k_b    = (const float*)d_in[10];
    const float* v_w    = (const float*)d_in[11];
    const float* v_b    = (const float*)d_in[12];
    const float* o_w    = (const float*)d_in[13];
    const float* o_b    = (const float*)d_in[14];
    const float* f_ln_w = (const float*)d_in[15];
    const float* f_ln_b = (const float*)d_in[16];
    const float* f_w    = (const float*)d_in[17];
    const float* f_b    = (const float*)d_in[18];

    // exact CTA count for the (qtile, chunk) decomposition
    int total = 0;
    for (int bx = 0; bx < Lc / TQ3; ++bx) {
        int l0 = Lc - TQ3 * (bx + 1);
        int emax = 6 * ((l0 + TQ3 - 1) / 6) + 6;
        total += (emax + CHUNK - 1) / CHUNK;
    }

    qkv_gate_kernel<<<(Bc * Lc) / QTOK, 128>>>(x, g_ln_w, g_ln_b, g_w1, g_b1,
                                               g_w2, g_b2, q_w, q_b, k_w, k_b,
                                               v_w, v_b);
    scan_sv_kernel<<<Bc * HIDc, Tt>>>();
    attn_kernel<<<dim3(total, NHc, Bc), 128>>>();
    combine_kernel<<<Bc * Tt, 128>>>();
    final_kernel<<<(Bc * Tt) / FTOK, 256>>>(o_w, o_b, f_ln_w, f_ln_b, f_w, f_b,
                                            (float*)d_out);
}

// round 14
// speedup vs baseline: 1.2215x; 1.0756x over previous
#include <cuda_runtime.h>
#include <cuda_fp16.h>
#include <math.h>

// Problem constants
#define Bc   2
#define Tt   512
#define Nf   6
#define Dd   32
#define HIDc 128
#define NHc  4
#define HDc  32
#define Lc   3072      // Tt*Nf
#define GHc  32
#define FDc  128
#define EPSc 1e-5f

#define NCHUNK 6
#define CHUNK  512
#define SHIFT2 12.0f   // uniform log2-domain score shift (cancels in sum o / sum su)
#define LOG2E  1.4426950408889634f

// NOTE on the reference's max(softmax, 1e-9): masked-tail term contributes
// ~1e-9 * sum(V) ~ 3e-8 absolute (~3e-7 relative) and in-window probabilities
// are always >= ~2e-7 >> 1e-9, so the clamp is numerically invisible at the
// 1e-3 threshold (current fp16 noise floor is 8e-5). It is omitted.

// Scratch (device globals: no allocation allowed)
__device__ __half d_Qh[Bc*NHc*Lc*HDc];   // fp16 Q (pre-scaled by log2e/sqrt(HD)) [bh][l][d]
__device__ __half d_Kh[Bc*NHc*Lc*HDc];   // fp16 K [bh][l][d]
__device__ __half d_Vt[Bc*NHc*HDc*Lc];   // fp16 V transposed [bh][d][l]
__device__ float  d_part[NCHUNK*Bc*Lc*HIDc]; // unnormalized attention partials
__device__ float  d_psum[NCHUNK*Bc*NHc*Lc];  // softmax denominator partials
__device__ float  d_SP[Bc*Tt*HIDc];      // pooled attention rows (pre o_w)

// D(16x8) += A(16x16,f16) * B(16x8,f16), fp32 accum.
__device__ __forceinline__ void mma_f16(float c[4],
    unsigned a0, unsigned a1, unsigned a2, unsigned a3,
    unsigned b0, unsigned b1)
{
    asm volatile(
        "mma.sync.aligned.m16n8k16.row.col.f32.f16.f16.f32 "
        "{%0,%1,%2,%3}, {%4,%5,%6,%7}, {%8,%9}, {%0,%1,%2,%3};"
        : "+f"(c[0]), "+f"(c[1]), "+f"(c[2]), "+f"(c[3])
        : "r"(a0), "r"(a1), "r"(a2), "r"(a3), "r"(b0), "r"(b1));
}

// packed fp16 2^x
__device__ __forceinline__ unsigned ex2_f16x2(float x0, float x1) {
    unsigned in, out;
    asm("cvt.rn.f16x2.f32 %0, %2, %1;" : "=r"(in) : "f"(x0), "f"(x1));
    asm("ex2.approx.f16x2 %0, %1;" : "=r"(out) : "r"(in));
    return out;
}

// ---------------------------------------------------------------------------
// Fused gater + gated QKV. One block (128 threads) per 16 tokens.
#define QTOK 16
__global__ __launch_bounds__(128) void qkv_gate_kernel(const float* __restrict__ x,
    const float* __restrict__ g_ln_w, const float* __restrict__ g_ln_b,
    const float* __restrict__ g_w1,   const float* __restrict__ g_b1,
    const float* __restrict__ g_w2,   const float* __restrict__ g_b2,
    const float* __restrict__ q_w,    const float* __restrict__ q_b,
    const float* __restrict__ k_w,    const float* __restrict__ k_b,
    const float* __restrict__ v_w,    const float* __restrict__ v_b)
{
    const float SC = 0.17677669529663688f * LOG2E;  // log2e/sqrt(32)
    int t0 = blockIdx.x * QTOK;
    int tid = threadIdx.x;
    int w = tid >> 5, lane = tid & 31;

    __shared__ float xs[QTOK][32];
    __shared__ float xns[QTOK][32];
    __shared__ float gate[QTOK];

    #pragma unroll
    for (int i = tid; i < QTOK*32; i += 128)
        xs[i >> 5][i & 31] = x[(size_t)t0 * 32 + i];
    __syncthreads();

    // LayerNorm for gater input (warp w: tokens 4w..4w+3)
    #pragma unroll
    for (int kk = 0; kk < 4; ++kk) {
        int t = w * 4 + kk;
        float xv = xs[t][lane];
        float s = xv, s2 = xv * xv;
        #pragma unroll
        for (int o = 16; o; o >>= 1) {
            s  += __shfl_xor_sync(0xffffffffu, s,  o);
            s2 += __shfl_xor_sync(0xffffffffu, s2, o);
        }
        float mu  = s * (1.0f / 32.0f);
        float var = s2 * (1.0f / 32.0f) - mu * mu;
        xns[t][lane] = (xv - mu) * rsqrtf(var + EPSc) * g_ln_w[lane] + g_ln_b[lane];
    }
    __syncthreads();

    // gater MLP (smem-broadcast matmul)
    #pragma unroll
    for (int kk = 0; kk < 4; ++kk) {
        int t = w * 4 + kk;
        float h = g_b1[lane];
        #pragma unroll
        for (int d = 0; d < 32; ++d)
            h += xns[t][d] * g_w1[d * GHc + lane];
        h = h / (1.0f + __expf(-h));
        float gp = h * g_w2[lane];
        #pragma unroll
        for (int o = 16; o; o >>= 1) gp += __shfl_xor_sync(0xffffffffu, gp, o);
        if (lane == 0) gate[t] = 1.0f / (1.0f + __expf(-(gp + g_b2[0])));
    }
    __syncthreads();

    int c = tid;
    float q[QTOK], k[QTOK], v[QTOK];
    float qb = q_b[c], kb = k_b[c], vb = v_b[c];
    #pragma unroll
    for (int t = 0; t < QTOK; ++t) { q[t] = qb; k[t] = kb; v[t] = vb; }
    #pragma unroll
    for (int dd = 0; dd < 32; ++dd) {
        float wq = q_w[dd * HIDc + c];
        float wk = k_w[dd * HIDc + c];
        float wv = v_w[dd * HIDc + c];
        #pragma unroll
        for (int t = 0; t < QTOK; ++t) {
            float xd = xs[t][dd];
            q[t] += xd * wq; k[t] += xd * wk; v[t] += xd * wv;
        }
    }

    int hh = c >> 5, d2 = c & 31;
    int b = t0 / Lc, lbase = t0 - b * Lc;
    int bh = b * NHc + hh;

    union { __half h[QTOK]; uint4 u[2]; } vp;
    #pragma unroll
    for (int t = 0; t < QTOK; ++t) {
        float g = gate[t];
        size_t idx = ((size_t)bh * Lc + lbase + t) * HDc + d2;
        d_Qh[idx] = __float2half_rn(q[t] * g * SC);
        d_Kh[idx] = __float2half_rn(k[t] * g);
        vp.h[t]   = __float2half_rn(v[t] * g);
    }
    uint4* vdst = (uint4*)&d_Vt[((size_t)bh * HDc + d2) * Lc + lbase];
    vdst[0] = vp.u[0];
    vdst[1] = vp.u[1];
}

// ---------------------------------------------------------------------------
// Tensor-core block-causal attention: fp16 scoring + fp16 PV (fp32 accum),
// split-K over 512-key chunks; scores in log2 domain, p = 2^(s - 12) via
// ex2.approx.f16x2 (shift cancels in sum o / sum su).
// 128 threads, 4 warps x 16 queries = 64 queries/CTA, 32-key tiles.
#define TQ3 64
#define TK3 32
#define KSTH 40  // K smem row stride (halves)
#define VSTR 40  // V^T smem row stride (halves)
#define PSTR 40  // psh row stride (halves)
__global__ __launch_bounds__(128, 7) void attn_kernel()
{
    // map blockIdx.x -> (qtile bx, key chunk)
    int id = blockIdx.x;
    int bx = 0, l0, emax;
    for (;;) {
        l0 = Lc - TQ3 * (bx + 1);
        emax = 6 * ((l0 + TQ3 - 1) / 6) + 6;
        int nch = (emax + CHUNK - 1) / CHUNK;
        if (id < nch) break;
        id -= nch; ++bx;
    }
    int chunk = id;
    int h  = blockIdx.y;
    int b  = blockIdx.z;
    int bh = b * NHc + h;

    const __half* Qb = d_Qh + (size_t)bh * Lc * HDc;
    const __half* Kb = d_Kh + (size_t)bh * Lc * HDc;
    const __half* Vt = d_Vt + (size_t)bh * HDc * Lc;
    float* partp = d_part + (size_t)chunk * (Bc*Lc*HIDc);

    __shared__ __align__(16) __half Ksh[TK3 * KSTH];   // [key][dim]
    __shared__ __align__(16) __half Vsh[HDc * VSTR];   // [dim(32)][key(32)]
    __shared__ __align__(16) __half psh[TQ3 * PSTR];   // [query][key] fp16

    int tid  = threadIdx.x;
    int w    = tid >> 5;
    int lane = tid & 31;
    int g    = lane >> 2;        // groupID
    int tig  = lane & 3;         // thread-in-group
    int qbase = w * 16;

    // Q A-fragments (fp16, k16 steps s=0,1), held in registers
    unsigned qa[2][4];
    const __half* Qp = Qb + (size_t)(l0 + qbase) * 32;
    #pragma unroll
    for (int s = 0; s < 2; ++s) {
        qa[s][0] = *(const unsigned*)(Qp + (size_t)g * 32 + 16*s + 2*tig);
        qa[s][1] = *(const unsigned*)(Qp + (size_t)(g + 8) * 32 + 16*s + 2*tig);
        qa[s][2] = *(const unsigned*)(Qp + (size_t)g * 32 + 16*s + 2*tig + 8);
        qa[s][3] = *(const unsigned*)(Qp + (size_t)(g + 8) * 32 + 16*s + 2*tig + 8);
    }

    int endA = 6 * ((l0 + qbase + g) / 6) + 6;        // causal end, row g
    int endB = 6 * ((l0 + qbase + g + 8) / 6) + 6;    // causal end, row g+8
    int wend = 6 * ((l0 + qbase + 15) / 6) + 6;       // warp's max end

    int kstart = chunk * CHUNK;
    int kend   = min(emax, kstart + CHUNK);           // CTA's chunk range

    float o[2][2][4] = {};       // O^T accum [md][nq][reg]
    float su_lo = 0.f, su_hi = 0.f;

    // tile loader mapping: 128 thr -> 32 rows x 8 halves each
    int trow = tid >> 2;
    int tcol = (tid & 3) * 8;

    uint4 kA = *(const uint4*)(Kb + (size_t)(kstart + trow) * 32 + tcol);
    uint4 vA = *(const uint4*)(Vt + (size_t)trow * Lc + kstart + tcol);

    for (int kb = kstart; kb < kend; kb += TK3) {
        __syncthreads();
        *(uint4*)(Ksh + trow * KSTH + tcol) = kA;
        *(uint4*)(Vsh + trow * VSTR + tcol) = vA;
        if (kb + TK3 < kend) {
            kA = *(const uint4*)(Kb + (size_t)(kb + TK3 + trow) * 32 + tcol);
            vA = *(const uint4*)(Vt + (size_t)trow * Lc + kb + TK3 + tcol);
        }
        __syncthreads();
        if (kb >= wend) continue;   // this warp done; still hits barriers

        // ---- scoring: S(16q x 32k) = Q * K^T via fp16 mma, per 8-key tile j ----
        #pragma unroll
        for (int j = 0; j < 4; ++j) {
            float c[4] = {0.f, 0.f, 0.f, 0.f};
            const __half* kr = Ksh + (8*j + g) * KSTH;
            #pragma unroll
            for (int s = 0; s < 2; ++s) {
                unsigned b0 = *(const unsigned*)(kr + 16*s + 2*tig);
                unsigned b1 = *(const unsigned*)(kr + 16*s + 2*tig + 8);
                mma_f16(c, qa[s][0], qa[s][1], qa[s][2], qa[s][3], b0, b1);
            }
            int ke = kb + 8*j + 2*tig;
            // p = 2^(s - 12) in fp16 pairs; causal mask by zeroing fp16 lanes
            unsigned pA = ex2_f16x2(c[0] - SHIFT2, c[1] - SHIFT2);
            unsigned pB = ex2_f16x2(c[2] - SHIFT2, c[3] - SHIFT2);
            unsigned mA = (ke < endA ? 0xFFFFu : 0u) | (ke + 1 < endA ? 0xFFFF0000u : 0u);
            unsigned mB = (ke < endB ? 0xFFFFu : 0u) | (ke + 1 < endB ? 0xFFFF0000u : 0u);
            pA &= mA;
            pB &= mB;
            float2 fA = __half22float2(*(__half2*)&pA);
            float2 fB = __half22float2(*(__half2*)&pB);
            su_lo += fA.x + fA.y;
            su_hi += fB.x + fB.y;
            *(unsigned*)(psh + (qbase + g) * PSTR + 8*j + 2*tig)     = pA;
            *(unsigned*)(psh + (qbase + g + 8) * PSTR + 8*j + 2*tig) = pB;
        }
        __syncwarp();

        // ---- PV: O^T(32d x 16q) += V^T * P^T via fp16 mma ----
        #pragma unroll
        for (int s = 0; s < 2; ++s) {
            unsigned pb00 = *(const unsigned*)(psh + (qbase + g) * PSTR + 16*s + 2*tig);
            unsigned pb01 = *(const unsigned*)(psh + (qbase + g) * PSTR + 16*s + 2*tig + 8);
            unsigned pb10 = *(const unsigned*)(psh + (qbase + 8 + g) * PSTR + 16*s + 2*tig);
            unsigned pb11 = *(const unsigned*)(psh + (qbase + 8 + g) * PSTR + 16*s + 2*tig + 8);
            #pragma unroll
            for (int md = 0; md < 2; ++md) {
                const __half* v0 = Vsh + (16*md + g) * VSTR;
                const __half* v1 = Vsh + (16*md + g + 8) * VSTR;
                unsigned a0 = *(const unsigned*)(v0 + 16*s + 2*tig);
                unsigned a1 = *(const unsigned*)(v1 + 16*s + 2*tig);
                unsigned a2 = *(const unsigned*)(v0 + 16*s + 2*tig + 8);
                unsigned a3 = *(const unsigned*)(v1 + 16*s + 2*tig + 8);
                mma_f16(o[md][0], a0, a1, a2, a3, pb00, pb01);
                mma_f16(o[md][1], a0, a1, a2, a3, pb10, pb11);
            }
        }
        __syncwarp();
    }

    // reduce denominator partials within each quad (over tig)
    su_lo += __shfl_xor_sync(0xffffffffu, su_lo, 1);
    su_lo += __shfl_xor_sync(0xffffffffu, su_lo, 2);
    su_hi += __shfl_xor_sync(0xffffffffu, su_hi, 1);
    su_hi += __shfl_xor_sync(0xffffffffu, su_hi, 2);
    if (tig == 0) {
        size_t sb = (size_t)chunk * (Bc*NHc*Lc) + (size_t)bh * Lc + l0 + qbase;
        d_psum[sb + g]     = su_lo;
        d_psum[sb + g + 8] = su_hi;
    }

    #pragma unroll
    for (int md = 0; md < 2; ++md) {
        #pragma unroll
        for (int nq = 0; nq < 2; ++nq) {
            int qloc = qbase + 8*nq + 2*tig;
            size_t base = ((size_t)b * Lc + l0 + qloc) * HIDc + h * HDc + 16*md + g;
            partp[base]            = o[md][nq][0];
            partp[base + HIDc]     = o[md][nq][1];
            partp[base + 8]        = o[md][nq][2];
            partp[base + HIDc + 8] = o[md][nq][3];
        }
    }
}

// ---------------------------------------------------------------------------
// Combine split-K partials + pool(6) -> d_SP.
// grid = Bc*Tt blocks x 128 threads; fully unrolled independent loads.
__global__ __launch_bounds__(128) void combine_kernel()
{
    int bt = blockIdx.x;
    int b = bt / Tt, tt = bt - b * Tt;
    int c = threadIdx.x;
    int h = c >> 5;

    int end = tt * Nf + Nf;
    int nc = (end + CHUNK - 1) / CHUNK;   // live chunks for this time block

    float p = 0.0f;
    #pragma unroll
    for (int k = 0; k < Nf; ++k) {
        int l = tt * Nf + k;
        float su = 0.f, oo = 0.f;
        #pragma unroll
        for (int cc = 0; cc < NCHUNK; ++cc) {
            if (cc < nc) {
                su += d_psum[(size_t)cc * (Bc*NHc*Lc) + ((size_t)b*NHc + h)*Lc + l];
                oo += d_part[(size_t)cc * (Bc*Lc*HIDc) + ((size_t)b*Lc + l)*HIDc + c];
            }
        }
        p += oo / su;
    }
    d_SP[(size_t)bt * HIDc + c] = p * (1.0f / Nf);
}

// ---------------------------------------------------------------------------
// o_w -> LN -> f_w -> SiLU on pooled rows.
// 4 rows per block, 256 blocks, 256 threads: the dd (reduction) dimension is
// split across the two 128-thread halves; partials reduced through smem.
#define FTOK 4
__global__ __launch_bounds__(256) void final_kernel(
    const float* __restrict__ o_w,    const float* __restrict__ o_b,
    const float* __restrict__ f_ln_w, const float* __restrict__ f_ln_b,
    const float* __restrict__ f_w,    const float* __restrict__ f_b,
    float* __restrict__ out)
{
    int p0 = blockIdx.x * FTOK;
    int tid = threadIdx.x;
    int c = tid & 127;
    int half = tid >> 7;
    int w = c >> 5, lane = c & 31;
    int d0 = half * 64;

    __shared__ float sp[FTOK][128];
    __shared__ float pacc[2][FTOK][128];
    __shared__ float sln[FTOK][128];
    __shared__ float redA[FTOK][4], redB[FTOK][4];

    #pragma unroll
    for (int i = tid; i < FTOK * 128; i += 256)
        ((float*)sp)[i] = d_SP[(size_t)p0 * HIDc + i];
    __syncthreads();

    // ---- o_w matmul, dd split across halves ----
    float acc[FTOK] = {0.f, 0.f, 0.f, 0.f};
    #pragma unroll 8
    for (int dd = d0; dd < d0 + 64; ++dd) {
        float wv = o_w[dd * HIDc + c];
        #pragma unroll
        for (int t = 0; t < FTOK; ++t) acc[t] += sp[t][dd] * wv;
    }
    #pragma unroll
    for (int t = 0; t < FTOK; ++t) pacc[half][t][c] = acc[t];
    __syncthreads();

    float o[FTOK];
    #pragma unroll
    for (int t = 0; t < FTOK; ++t)
        o[t] = pacc[0][t][c] + pacc[1][t][c] + o_b[c];

    // ---- LayerNorm stats (half 0 only) ----
    if (half == 0) {
        #pragma unroll
        for (int t = 0; t < FTOK; ++t) {
            float s = o[t], s2 = o[t] * o[t];
            #pragma unroll
            for (int off = 16; off; off >>= 1) {
                s  += __shfl_xor_sync(0xffffffffu, s,  off);
                s2 += __shfl_xor_sync(0xffffffffu, s2, off);
            }
            if (lane == 0) { redA[t][w] = s; redB[t][w] = s2; }
        }
    }
    __syncthreads();
    if (half == 0) {
        #pragma unroll
        for (int t = 0; t < FTOK; ++t) {
            float S  = redA[t][0] + redA[t][1] + redA[t][2] + redA[t][3];
            float S2 = redB[t][0] + redB[t][1] + redB[t][2] + redB[t][3];
            float mu  = S * (1.0f / 128.0f);
            float var = S2 * (1.0f / 128.0f) - mu * mu;
            sln[t][c] = (o[t] - mu) * rsqrtf(var + EPSc) * f_ln_w[c] + f_ln_b[c];
        }
    }
    __syncthreads();

    // ---- f_w matmul, dd split across halves ----
    float f[FTOK] = {0.f, 0.f, 0.f, 0.f};
    #pragma unroll 8
    for (int dd = d0; dd < d0 + 64; ++dd) {
        float wv = f_w[dd * HIDc + c];
        #pragma unroll
        for (int t = 0; t < FTOK; ++t) f[t] += sln[t][dd] * wv;
    }
    #pragma unroll
    for (int t = 0; t < FTOK; ++t) pacc[half][t][c] = f[t];
    __syncthreads();

    if (half == 0) {
        #pragma unroll
        for (int t = 0; t < FTOK; ++t) {
            float ff = pacc[0][t][c] + pacc[1][t][c] + f_b[c];
            out[(size_t)(p0 + t) * FDc + c] = ff / (1.0f + __expf(-ff));
        }
    }
}

// ---------------------------------------------------------------------------
extern "C" void kernel_launch(void* const* d_in, const int* in_sizes, int n_in,
                              void* d_out, int out_size)
{
    const float* x      = (const float*)d_in[0];
    const float* g_ln_w = (const float*)d_in[1];
    const float* g_ln_b = (const float*)d_in[2];
    const float* g_w1   = (const float*)d_in[3];
    const float* g_b1   = (const float*)d_in[4];
    const float* g_w2   = (const float*)d_in[5];
    const float* g_b2   = (const float*)d_in[6];
    const float* q_w    = (const float*)d_in[7];
    const float* q_b    = (const float*)d_in[8];
    const float* k_w    = (const float*)d_in[9];
    const float* k_b    = (const float*)d_in[10];
    const float* v_w    = (const float*)d_in[11];
    const float* v_b    = (const float*)d_in[12];
    const float* o_w    = (const float*)d_in[13];
    const float* o_b    = (const float*)d_in[14];
    const float* f_ln_w = (const float*)d_in[15];
    const float* f_ln_b = (const float*)d_in[16];
    const float* f_w    = (const float*)d_in[17];
    const float* f_b    = (const float*)d_in[18];

    // exact CTA count for the (qtile, chunk) decomposition
    int total = 0;
    for (int bx = 0; bx < Lc / TQ3; ++bx) {
        int l0 = Lc - TQ3 * (bx + 1);
        int emax = 6 * ((l0 + TQ3 - 1) / 6) + 6;
        total += (emax + CHUNK - 1) / CHUNK;
    }

    qkv_gate_kernel<<<(Bc * Lc) / QTOK, 128>>>(x, g_ln_w, g_ln_b, g_w1, g_b1,
                                               g_w2, g_b2, q_w, q_b, k_w, k_b,
                                               v_w, v_b);
    attn_kernel<<<dim3(total, NHc, Bc), 128>>>();
    combine_kernel<<<Bc * Tt, 128>>>();
    final_kernel<<<(Bc * Tt) / FTOK, 256>>>(o_w, o_b, f_ln_w, f_ln_b, f_w, f_b,
                                            (float*)d_out);
}

// round 15
// speedup vs baseline: 1.2437x; 1.0182x over previous
#include <cuda_runtime.h>
#include <cuda_fp16.h>
#include <math.h>

// Problem constants
#define Bc   2
#define Tt   512
#define Nf   6
#define Dd   32
#define HIDc 128
#define NHc  4
#define HDc  32
#define Lc   3072      // Tt*Nf
#define GHc  32
#define FDc  128
#define EPSc 1e-5f

#define NCHUNK 6
#define CHUNK  512
#define SHIFT2 12.0f   // uniform log2-domain score shift (cancels in sum o / sum su)
#define LOG2E  1.4426950408889634f

// NOTE on the reference's max(softmax, 1e-9): masked-tail term contributes
// ~1e-9 * sum(V) ~ 3e-8 absolute (~3e-7 relative) and in-window probabilities
// are always >= ~2e-7 >> 1e-9, so the clamp is numerically invisible at the
// 1e-3 threshold (current fp16 noise floor is 8e-5). It is omitted.

// Scratch (device globals: no allocation allowed)
__device__ __half d_Qh[Bc*NHc*Lc*HDc];   // fp16 Q (pre-scaled by log2e/sqrt(HD)) [bh][l][d]
__device__ __half d_Kh[Bc*NHc*Lc*HDc];   // fp16 K [bh][l][d]
__device__ __half d_Vt[Bc*NHc*HDc*Lc];   // fp16 V transposed [bh][d][l]
__device__ float  d_part[NCHUNK*Bc*Lc*HIDc]; // unnormalized attention partials
__device__ float  d_psum[NCHUNK*Bc*NHc*Lc];  // softmax denominator partials
__device__ float  d_SP[Bc*Tt*HIDc];      // pooled attention rows (pre o_w)

// D(16x8) += A(16x16,f16) * B(16x8,f16), fp32 accum.
__device__ __forceinline__ void mma_f16(float c[4],
    unsigned a0, unsigned a1, unsigned a2, unsigned a3,
    unsigned b0, unsigned b1)
{
    asm volatile(
        "mma.sync.aligned.m16n8k16.row.col.f32.f16.f16.f32 "
        "{%0,%1,%2,%3}, {%4,%5,%6,%7}, {%8,%9}, {%0,%1,%2,%3};"
        : "+f"(c[0]), "+f"(c[1]), "+f"(c[2]), "+f"(c[3])
        : "r"(a0), "r"(a1), "r"(a2), "r"(a3), "r"(b0), "r"(b1));
}

// packed fp16 2^x
__device__ __forceinline__ unsigned ex2_f16x2(float x0, float x1) {
    unsigned in, out;
    asm("cvt.rn.f16x2.f32 %0, %2, %1;" : "=r"(in) : "f"(x0), "f"(x1));
    asm("ex2.approx.f16x2 %0, %1;" : "=r"(out) : "r"(in));
    return out;
}

// ---------------------------------------------------------------------------
// Fused gater + gated QKV. One block (128 threads) per 16 tokens.
#define QTOK 16
__global__ __launch_bounds__(128) void qkv_gate_kernel(const float* __restrict__ x,
    const float* __restrict__ g_ln_w, const float* __restrict__ g_ln_b,
    const float* __restrict__ g_w1,   const float* __restrict__ g_b1,
    const float* __restrict__ g_w2,   const float* __restrict__ g_b2,
    const float* __restrict__ q_w,    const float* __restrict__ q_b,
    const float* __restrict__ k_w,    const float* __restrict__ k_b,
    const float* __restrict__ v_w,    const float* __restrict__ v_b)
{
    const float SC = 0.17677669529663688f * LOG2E;  // log2e/sqrt(32)
    int t0 = blockIdx.x * QTOK;
    int tid = threadIdx.x;
    int w = tid >> 5, lane = tid & 31;

    __shared__ float xs[QTOK][32];
    __shared__ float xns[QTOK][32];
    __shared__ float gate[QTOK];

    #pragma unroll
    for (int i = tid; i < QTOK*32; i += 128)
        xs[i >> 5][i & 31] = x[(size_t)t0 * 32 + i];
    __syncthreads();

    // LayerNorm for gater input (warp w: tokens 4w..4w+3)
    #pragma unroll
    for (int kk = 0; kk < 4; ++kk) {
        int t = w * 4 + kk;
        float xv = xs[t][lane];
        float s = xv, s2 = xv * xv;
        #pragma unroll
        for (int o = 16; o; o >>= 1) {
            s  += __shfl_xor_sync(0xffffffffu, s,  o);
            s2 += __shfl_xor_sync(0xffffffffu, s2, o);
        }
        float mu  = s * (1.0f / 32.0f);
        float var = s2 * (1.0f / 32.0f) - mu * mu;
        xns[t][lane] = (xv - mu) * rsqrtf(var + EPSc) * g_ln_w[lane] + g_ln_b[lane];
    }
    __syncthreads();

    // gater MLP (smem-broadcast matmul)
    #pragma unroll
    for (int kk = 0; kk < 4; ++kk) {
        int t = w * 4 + kk;
        float h = g_b1[lane];
        #pragma unroll
        for (int d = 0; d < 32; ++d)
            h += xns[t][d] * g_w1[d * GHc + lane];
        h = h / (1.0f + __expf(-h));
        float gp = h * g_w2[lane];
        #pragma unroll
        for (int o = 16; o; o >>= 1) gp += __shfl_xor_sync(0xffffffffu, gp, o);
        if (lane == 0) gate[t] = 1.0f / (1.0f + __expf(-(gp + g_b2[0])));
    }
    __syncthreads();

    int c = tid;
    float q[QTOK], k[QTOK], v[QTOK];
    float qb = q_b[c], kb = k_b[c], vb = v_b[c];
    #pragma unroll
    for (int t = 0; t < QTOK; ++t) { q[t] = qb; k[t] = kb; v[t] = vb; }
    #pragma unroll
    for (int dd = 0; dd < 32; ++dd) {
        float wq = q_w[dd * HIDc + c];
        float wk = k_w[dd * HIDc + c];
        float wv = v_w[dd * HIDc + c];
        #pragma unroll
        for (int t = 0; t < QTOK; ++t) {
            float xd = xs[t][dd];
            q[t] += xd * wq; k[t] += xd * wk; v[t] += xd * wv;
        }
    }

    int hh = c >> 5, d2 = c & 31;
    int b = t0 / Lc, lbase = t0 - b * Lc;
    int bh = b * NHc + hh;

    union { __half h[QTOK]; uint4 u[2]; } vp;
    #pragma unroll
    for (int t = 0; t < QTOK; ++t) {
        float g = gate[t];
        size_t idx = ((size_t)bh * Lc + lbase + t) * HDc + d2;
        d_Qh[idx] = __float2half_rn(q[t] * g * SC);
        d_Kh[idx] = __float2half_rn(k[t] * g);
        vp.h[t]   = __float2half_rn(v[t] * g);
    }
    uint4* vdst = (uint4*)&d_Vt[((size_t)bh * HDc + d2) * Lc + lbase];
    vdst[0] = vp.u[0];
    vdst[1] = vp.u[1];
}

// ---------------------------------------------------------------------------
// Tensor-core block-causal attention: fp16 scoring + fp16 PV (fp32 accum),
// split-K over 512-key chunks; scores in log2 domain, p = 2^(s - 12) via
// ex2.approx.f16x2 (shift cancels in sum o / sum su).
// 128 threads, 4 warps x 16 queries = 64 queries/CTA, 32-key tiles.
#define TQ3 64
#define TK3 32
#define KSTH 40  // K smem row stride (halves)
#define VSTR 40  // V^T smem row stride (halves)
#define PSTR 40  // psh row stride (halves)
__global__ __launch_bounds__(128, 7) void attn_kernel()
{
    // map blockIdx.x -> (qtile bx, key chunk)
    int id = blockIdx.x;
    int bx = 0, l0, emax;
    for (;;) {
        l0 = Lc - TQ3 * (bx + 1);
        emax = 6 * ((l0 + TQ3 - 1) / 6) + 6;
        int nch = (emax + CHUNK - 1) / CHUNK;
        if (id < nch) break;
        id -= nch; ++bx;
    }
    int chunk = id;
    int h  = blockIdx.y;
    int b  = blockIdx.z;
    int bh = b * NHc + h;

    const __half* Qb = d_Qh + (size_t)bh * Lc * HDc;
    const __half* Kb = d_Kh + (size_t)bh * Lc * HDc;
    const __half* Vt = d_Vt + (size_t)bh * HDc * Lc;
    float* partp = d_part + (size_t)chunk * (Bc*Lc*HIDc);

    __shared__ __align__(16) __half Ksh[TK3 * KSTH];   // [key][dim]
    __shared__ __align__(16) __half Vsh[HDc * VSTR];   // [dim(32)][key(32)]
    __shared__ __align__(16) __half psh[TQ3 * PSTR];   // [query][key] fp16

    int tid  = threadIdx.x;
    int w    = tid >> 5;
    int lane = tid & 31;
    int g    = lane >> 2;        // groupID
    int tig  = lane & 3;         // thread-in-group
    int qbase = w * 16;

    // Q A-fragments (fp16, k16 steps s=0,1), held in registers
    unsigned qa[2][4];
    const __half* Qp = Qb + (size_t)(l0 + qbase) * 32;
    #pragma unroll
    for (int s = 0; s < 2; ++s) {
        qa[s][0] = *(const unsigned*)(Qp + (size_t)g * 32 + 16*s + 2*tig);
        qa[s][1] = *(const unsigned*)(Qp + (size_t)(g + 8) * 32 + 16*s + 2*tig);
        qa[s][2] = *(const unsigned*)(Qp + (size_t)g * 32 + 16*s + 2*tig + 8);
        qa[s][3] = *(const unsigned*)(Qp + (size_t)(g + 8) * 32 + 16*s + 2*tig + 8);
    }

    int endA = 6 * ((l0 + qbase + g) / 6) + 6;        // causal end, row g
    int endB = 6 * ((l0 + qbase + g + 8) / 6) + 6;    // causal end, row g+8
    int wend = 6 * ((l0 + qbase + 15) / 6) + 6;       // warp's max end

    int kstart = chunk * CHUNK;
    int kend   = min(emax, kstart + CHUNK);           // CTA's chunk range

    float o[2][2][4] = {};       // O^T accum [md][nq][reg]
    float su_lo = 0.f, su_hi = 0.f;

    // tile loader mapping: 128 thr -> 32 rows x 8 halves each
    int trow = tid >> 2;
    int tcol = (tid & 3) * 8;

    uint4 kA = *(const uint4*)(Kb + (size_t)(kstart + trow) * 32 + tcol);
    uint4 vA = *(const uint4*)(Vt + (size_t)trow * Lc + kstart + tcol);

    for (int kb = kstart; kb < kend; kb += TK3) {
        __syncthreads();
        *(uint4*)(Ksh + trow * KSTH + tcol) = kA;
        *(uint4*)(Vsh + trow * VSTR + tcol) = vA;
        if (kb + TK3 < kend) {
            kA = *(const uint4*)(Kb + (size_t)(kb + TK3 + trow) * 32 + tcol);
            vA = *(const uint4*)(Vt + (size_t)trow * Lc + kb + TK3 + tcol);
        }
        __syncthreads();
        if (kb >= wend) continue;   // this warp done; still hits barriers

        // ---- scoring: S(16q x 32k) = Q * K^T via fp16 mma, per 8-key tile j ----
        #pragma unroll
        for (int j = 0; j < 4; ++j) {
            float c[4] = {0.f, 0.f, 0.f, 0.f};
            const __half* kr = Ksh + (8*j + g) * KSTH;
            #pragma unroll
            for (int s = 0; s < 2; ++s) {
                unsigned b0 = *(const unsigned*)(kr + 16*s + 2*tig);
                unsigned b1 = *(const unsigned*)(kr + 16*s + 2*tig + 8);
                mma_f16(c, qa[s][0], qa[s][1], qa[s][2], qa[s][3], b0, b1);
            }
            int ke = kb + 8*j + 2*tig;
            // p = 2^(s - 12) in fp16 pairs; causal mask by zeroing fp16 lanes
            unsigned pA = ex2_f16x2(c[0] - SHIFT2, c[1] - SHIFT2);
            unsigned pB = ex2_f16x2(c[2] - SHIFT2, c[3] - SHIFT2);
            unsigned mA = (ke < endA ? 0xFFFFu : 0u) | (ke + 1 < endA ? 0xFFFF0000u : 0u);
            unsigned mB = (ke < endB ? 0xFFFFu : 0u) | (ke + 1 < endB ? 0xFFFF0000u : 0u);
            pA &= mA;
            pB &= mB;
            float2 fA = __half22float2(*(__half2*)&pA);
            float2 fB = __half22float2(*(__half2*)&pB);
            su_lo += fA.x + fA.y;
            su_hi += fB.x + fB.y;
            *(unsigned*)(psh + (qbase + g) * PSTR + 8*j + 2*tig)     = pA;
            *(unsigned*)(psh + (qbase + g + 8) * PSTR + 8*j + 2*tig) = pB;
        }
        __syncwarp();

        // ---- PV: O^T(32d x 16q) += V^T * P^T via fp16 mma ----
        #pragma unroll
        for (int s = 0; s < 2; ++s) {
            unsigned pb00 = *(const unsigned*)(psh + (qbase + g) * PSTR + 16*s + 2*tig);
            unsigned pb01 = *(const unsigned*)(psh + (qbase + g) * PSTR + 16*s + 2*tig + 8);
            unsigned pb10 = *(const unsigned*)(psh + (qbase + 8 + g) * PSTR + 16*s + 2*tig);
            unsigned pb11 = *(const unsigned*)(psh + (qbase + 8 + g) * PSTR + 16*s + 2*tig + 8);
            #pragma unroll
            for (int md = 0; md < 2; ++md) {
                const __half* v0 = Vsh + (16*md + g) * VSTR;
                const __half* v1 = Vsh + (16*md + g + 8) * VSTR;
                unsigned a0 = *(const unsigned*)(v0 + 16*s + 2*tig);
                unsigned a1 = *(const unsigned*)(v1 + 16*s + 2*tig);
                unsigned a2 = *(const unsigned*)(v0 + 16*s + 2*tig + 8);
                unsigned a3 = *(const unsigned*)(v1 + 16*s + 2*tig + 8);
                mma_f16(o[md][0], a0, a1, a2, a3, pb00, pb01);
                mma_f16(o[md][1], a0, a1, a2, a3, pb10, pb11);
            }
        }
        __syncwarp();
    }

    // reduce denominator partials within each quad (over tig)
    su_lo += __shfl_xor_sync(0xffffffffu, su_lo, 1);
    su_lo += __shfl_xor_sync(0xffffffffu, su_lo, 2);
    su_hi += __shfl_xor_sync(0xffffffffu, su_hi, 1);
    su_hi += __shfl_xor_sync(0xffffffffu, su_hi, 2);
    if (tig == 0) {
        size_t sb = (size_t)chunk * (Bc*NHc*Lc) + (size_t)bh * Lc + l0 + qbase;
        d_psum[sb + g]     = su_lo;
        d_psum[sb + g + 8] = su_hi;
    }

    #pragma unroll
    for (int md = 0; md < 2; ++md) {
        #pragma unroll
        for (int nq = 0; nq < 2; ++nq) {
            int qloc = qbase + 8*nq + 2*tig;
            size_t base = ((size_t)b * Lc + l0 + qloc) * HIDc + h * HDc + 16*md + g;
            partp[base]            = o[md][nq][0];
            partp[base + HIDc]     = o[md][nq][1];
            partp[base + 8]        = o[md][nq][2];
            partp[base + HIDc + 8] = o[md][nq][3];
        }
    }
}

// ---------------------------------------------------------------------------
// Combine split-K partials + pool(6) -> d_SP.
// grid = Bc*Tt blocks x 128 threads; fully unrolled independent loads.
__global__ __launch_bounds__(128) void combine_kernel()
{
    int bt = blockIdx.x;
    int b = bt / Tt, tt = bt - b * Tt;
    int c = threadIdx.x;
    int h = c >> 5;

    int end = tt * Nf + Nf;
    int nc = (end + CHUNK - 1) / CHUNK;   // live chunks for this time block

    float p = 0.0f;
    #pragma unroll
    for (int k = 0; k < Nf; ++k) {
        int l = tt * Nf + k;
        float su = 0.f, oo = 0.f;
        #pragma unroll
        for (int cc = 0; cc < NCHUNK; ++cc) {
            if (cc < nc) {
                su += d_psum[(size_t)cc * (Bc*NHc*Lc) + ((size_t)b*NHc + h)*Lc + l];
                oo += d_part[(size_t)cc * (Bc*Lc*HIDc) + ((size_t)b*Lc + l)*HIDc + c];
            }
        }
        p += oo / su;
    }
    d_SP[(size_t)bt * HIDc + c] = p * (1.0f / Nf);
}

// ---------------------------------------------------------------------------
// o_w -> LN -> f_w -> SiLU on pooled rows.
// 2 rows per block, 512 blocks, 256 threads (dd reduction split in halves).
#define FTOK 2
__global__ __launch_bounds__(256) void final_kernel(
    const float* __restrict__ o_w,    const float* __restrict__ o_b,
    const float* __restrict__ f_ln_w, const float* __restrict__ f_ln_b,
    const float* __restrict__ f_w,    const float* __restrict__ f_b,
    float* __restrict__ out)
{
    int p0 = blockIdx.x * FTOK;
    int tid = threadIdx.x;
    int c = tid & 127;
    int half = tid >> 7;
    int w = c >> 5, lane = c & 31;
    int d0 = half * 64;

    __shared__ float sp[FTOK][128];
    __shared__ float pacc[2][FTOK][128];
    __shared__ float sln[FTOK][128];
    __shared__ float redA[FTOK][4], redB[FTOK][4];

    #pragma unroll
    for (int i = tid; i < FTOK * 128; i += 256)
        ((float*)sp)[i] = d_SP[(size_t)p0 * HIDc + i];
    __syncthreads();

    // ---- o_w matmul, dd split across halves ----
    float acc[FTOK] = {0.f, 0.f};
    #pragma unroll 8
    for (int dd = d0; dd < d0 + 64; ++dd) {
        float wv = o_w[dd * HIDc + c];
        #pragma unroll
        for (int t = 0; t < FTOK; ++t) acc[t] += sp[t][dd] * wv;
    }
    #pragma unroll
    for (int t = 0; t < FTOK; ++t) pacc[half][t][c] = acc[t];
    __syncthreads();

    float o[FTOK];
    #pragma unroll
    for (int t = 0; t < FTOK; ++t)
        o[t] = pacc[0][t][c] + pacc[1][t][c] + o_b[c];

    // ---- LayerNorm stats (half 0 only) ----
    if (half == 0) {
        #pragma unroll
        for (int t = 0; t < FTOK; ++t) {
            float s = o[t], s2 = o[t] * o[t];
            #pragma unroll
            for (int off = 16; off; off >>= 1) {
                s  += __shfl_xor_sync(0xffffffffu, s,  off);
                s2 += __shfl_xor_sync(0xffffffffu, s2, off);
            }
            if (lane == 0) { redA[t][w] = s; redB[t][w] = s2; }
        }
    }
    __syncthreads();
    if (half == 0) {
        #pragma unroll
        for (int t = 0; t < FTOK; ++t) {
            float S  = redA[t][0] + redA[t][1] + redA[t][2] + redA[t][3];
            float S2 = redB[t][0] + redB[t][1] + redB[t][2] + redB[t][3];
            float mu  = S * (1.0f / 128.0f);
            float var = S2 * (1.0f / 128.0f) - mu * mu;
            sln[t][c] = (o[t] - mu) * rsqrtf(var + EPSc) * f_ln_w[c] + f_ln_b[c];
        }
    }
    __syncthreads();

    // ---- f_w matmul, dd split across halves ----
    float f[FTOK] = {0.f, 0.f};
    #pragma unroll 8
    for (int dd = d0; dd < d0 + 64; ++dd) {
        float wv = f_w[dd * HIDc + c];
        #pragma unroll
        for (int t = 0; t < FTOK; ++t) f[t] += sln[t][dd] * wv;
    }
    #pragma unroll
    for (int t = 0; t < FTOK; ++t) pacc[half][t][c] = f[t];
    __syncthreads();

    if (half == 0) {
        #pragma unroll
        for (int t = 0; t < FTOK; ++t) {
            float ff = pacc[0][t][c] + pacc[1][t][c] + f_b[c];
            out[(size_t)(p0 + t) * FDc + c] = ff / (1.0f + __expf(-ff));
        }
    }
}

// ---------------------------------------------------------------------------
extern "C" void kernel_launch(void* const* d_in, const int* in_sizes, int n_in,
                              void* d_out, int out_size)
{
    const float* x      = (const float*)d_in[0];
    const float* g_ln_w = (const float*)d_in[1];
    const float* g_ln_b = (const float*)d_in[2];
    const float* g_w1   = (const float*)d_in[3];
    const float* g_b1   = (const float*)d_in[4];
    const float* g_w2   = (const float*)d_in[5];
    const float* g_b2   = (const float*)d_in[6];
    const float* q_w    = (const float*)d_in[7];
    const float* q_b    = (const float*)d_in[8];
    const float* k_w    = (const float*)d_in[9];
    const float* k_b    = (const float*)d_in[10];
    const float* v_w    = (const float*)d_in[11];
    const float* v_b    = (const float*)d_in[12];
    const float* o_w    = (const float*)d_in[13];
    const float* o_b    = (const float*)d_in[14];
    const float* f_ln_w = (const float*)d_in[15];
    const float* f_ln_b = (const float*)d_in[16];
    const float* f_w    = (const float*)d_in[17];
    const float* f_b    = (const float*)d_in[18];

    // exact CTA count for the (qtile, chunk) decomposition
    int total = 0;
    for (int bx = 0; bx < Lc / TQ3; ++bx) {
        int l0 = Lc - TQ3 * (bx + 1);
        int emax = 6 * ((l0 + TQ3 - 1) / 6) + 6;
        total += (emax + CHUNK - 1) / CHUNK;
    }

    qkv_gate_kernel<<<(Bc * Lc) / QTOK, 128>>>(x, g_ln_w, g_ln_b, g_w1, g_b1,
                                               g_w2, g_b2, q_w, q_b, k_w, k_b,
                                               v_w, v_b);
    attn_kernel<<<dim3(total, NHc, Bc), 128>>>();
    combine_kernel<<<Bc * Tt, 128>>>();
    final_kernel<<<(Bc * Tt) / FTOK, 256>>>(o_w, o_b, f_ln_w, f_ln_b, f_w, f_b,
                                            (float*)d_out);
}

// round 16
// speedup vs baseline: 1.2647x; 1.0168x over previous
#include <cuda_runtime.h>
#include <cuda_fp16.h>
#include <math.h>

// Problem constants
#define Bc   2
#define Tt   512
#define Nf   6
#define Dd   32
#define HIDc 128
#define NHc  4
#define HDc  32
#define Lc   3072      // Tt*Nf
#define GHc  32
#define FDc  128
#define EPSc 1e-5f

#define NCHUNK 6
#define CHUNK  512
#define SHIFT2 12.0f   // uniform log2-domain score shift (cancels in sum o / sum su)
#define LOG2E  1.4426950408889634f

// NOTE on the reference's max(softmax, 1e-9): masked-tail term contributes
// ~1e-9 * sum(V) ~ 3e-8 absolute (~3e-7 relative) and in-window probabilities
// are always >= ~2e-7 >> 1e-9, so the clamp is numerically invisible at the
// 1e-3 threshold. It is omitted.

// Scratch (device globals: no allocation allowed)
__device__ __half d_Qh[Bc*NHc*Lc*HDc];   // fp16 Q (pre-scaled by log2e/sqrt(HD)) [bh][l][d]
__device__ __half d_Kh[Bc*NHc*Lc*HDc];   // fp16 K [bh][l][d]
__device__ __half d_Vt[Bc*NHc*HDc*Lc];   // fp16 V transposed [bh][d][l]
__device__ __half d_parth[NCHUNK*Bc*Lc*HIDc]; // fp16 unnormalized attention partials
__device__ float  d_psum[NCHUNK*Bc*NHc*Lc];   // fp32 softmax denominator partials
__device__ float  d_SP[Bc*Tt*HIDc];      // pooled attention rows (pre o_w)

// D(16x8) += A(16x16,f16) * B(16x8,f16), fp32 accum.
__device__ __forceinline__ void mma_f16(float c[4],
    unsigned a0, unsigned a1, unsigned a2, unsigned a3,
    unsigned b0, unsigned b1)
{
    asm volatile(
        "mma.sync.aligned.m16n8k16.row.col.f32.f16.f16.f32 "
        "{%0,%1,%2,%3}, {%4,%5,%6,%7}, {%8,%9}, {%0,%1,%2,%3};"
        : "+f"(c[0]), "+f"(c[1]), "+f"(c[2]), "+f"(c[3])
        : "r"(a0), "r"(a1), "r"(a2), "r"(a3), "r"(b0), "r"(b1));
}

// packed fp16 2^x
__device__ __forceinline__ unsigned ex2_f16x2(float x0, float x1) {
    unsigned in, out;
    asm("cvt.rn.f16x2.f32 %0, %2, %1;" : "=r"(in) : "f"(x0), "f"(x1));
    asm("ex2.approx.f16x2 %0, %1;" : "=r"(out) : "r"(in));
    return out;
}

// ---------------------------------------------------------------------------
// Fused gater + gated QKV. One block (128 threads) per 16 tokens.
#define QTOK 16
__global__ __launch_bounds__(128) void qkv_gate_kernel(const float* __restrict__ x,
    const float* __restrict__ g_ln_w, const float* __restrict__ g_ln_b,
    const float* __restrict__ g_w1,   const float* __restrict__ g_b1,
    const float* __restrict__ g_w2,   const float* __restrict__ g_b2,
    const float* __restrict__ q_w,    const float* __restrict__ q_b,
    const float* __restrict__ k_w,    const float* __restrict__ k_b,
    const float* __restrict__ v_w,    const float* __restrict__ v_b)
{
    const float SC = 0.17677669529663688f * LOG2E;  // log2e/sqrt(32)
    int t0 = blockIdx.x * QTOK;
    int tid = threadIdx.x;
    int w = tid >> 5, lane = tid & 31;

    __shared__ float xs[QTOK][32];
    __shared__ float xns[QTOK][32];
    __shared__ float gate[QTOK];

    #pragma unroll
    for (int i = tid; i < QTOK*32; i += 128)
        xs[i >> 5][i & 31] = x[(size_t)t0 * 32 + i];
    __syncthreads();

    // LayerNorm for gater input (warp w: tokens 4w..4w+3)
    #pragma unroll
    for (int kk = 0; kk < 4; ++kk) {
        int t = w * 4 + kk;
        float xv = xs[t][lane];
        float s = xv, s2 = xv * xv;
        #pragma unroll
        for (int o = 16; o; o >>= 1) {
            s  += __shfl_xor_sync(0xffffffffu, s,  o);
            s2 += __shfl_xor_sync(0xffffffffu, s2, o);
        }
        float mu  = s * (1.0f / 32.0f);
        float var = s2 * (1.0f / 32.0f) - mu * mu;
        xns[t][lane] = (xv - mu) * rsqrtf(var + EPSc) * g_ln_w[lane] + g_ln_b[lane];
    }
    __syncthreads();

    // gater MLP (smem-broadcast matmul)
    #pragma unroll
    for (int kk = 0; kk < 4; ++kk) {
        int t = w * 4 + kk;
        float h = g_b1[lane];
        #pragma unroll
        for (int d = 0; d < 32; ++d)
            h += xns[t][d] * g_w1[d * GHc + lane];
        h = h / (1.0f + __expf(-h));
        float gp = h * g_w2[lane];
        #pragma unroll
        for (int o = 16; o; o >>= 1) gp += __shfl_xor_sync(0xffffffffu, gp, o);
        if (lane == 0) gate[t] = 1.0f / (1.0f + __expf(-(gp + g_b2[0])));
    }
    __syncthreads();

    int c = tid;
    float q[QTOK], k[QTOK], v[QTOK];
    float qb = q_b[c], kb = k_b[c], vb = v_b[c];
    #pragma unroll
    for (int t = 0; t < QTOK; ++t) { q[t] = qb; k[t] = kb; v[t] = vb; }
    #pragma unroll
    for (int dd = 0; dd < 32; ++dd) {
        float wq = q_w[dd * HIDc + c];
        float wk = k_w[dd * HIDc + c];
        float wv = v_w[dd * HIDc + c];
        #pragma unroll
        for (int t = 0; t < QTOK; ++t) {
            float xd = xs[t][dd];
            q[t] += xd * wq; k[t] += xd * wk; v[t] += xd * wv;
        }
    }

    int hh = c >> 5, d2 = c & 31;
    int b = t0 / Lc, lbase = t0 - b * Lc;
    int bh = b * NHc + hh;

    union { __half h[QTOK]; uint4 u[2]; } vp;
    #pragma unroll
    for (int t = 0; t < QTOK; ++t) {
        float g = gate[t];
        size_t idx = ((size_t)bh * Lc + lbase + t) * HDc + d2;
        d_Qh[idx] = __float2half_rn(q[t] * g * SC);
        d_Kh[idx] = __float2half_rn(k[t] * g);
        vp.h[t]   = __float2half_rn(v[t] * g);
    }
    uint4* vdst = (uint4*)&d_Vt[((size_t)bh * HDc + d2) * Lc + lbase];
    vdst[0] = vp.u[0];
    vdst[1] = vp.u[1];
}

// ---------------------------------------------------------------------------
// Tensor-core block-causal attention: fp16 scoring + fp16 PV (fp32 accum),
// split-K over 512-key chunks; scores in log2 domain, p = 2^(s - 12) via
// ex2.approx.f16x2 (shift cancels in sum o / sum su).
// 128 threads, 4 warps x 16 queries = 64 queries/CTA, 32-key tiles.
#define TQ3 64
#define TK3 32
#define KSTH 40  // K smem row stride (halves)
#define VSTR 40  // V^T smem row stride (halves)
#define PSTR 40  // psh row stride (halves)
__global__ __launch_bounds__(128, 7) void attn_kernel()
{
    // map blockIdx.x -> (qtile bx, key chunk)
    int id = blockIdx.x;
    int bx = 0, l0, emax;
    for (;;) {
        l0 = Lc - TQ3 * (bx + 1);
        emax = 6 * ((l0 + TQ3 - 1) / 6) + 6;
        int nch = (emax + CHUNK - 1) / CHUNK;
        if (id < nch) break;
        id -= nch; ++bx;
    }
    int chunk = id;
    int h  = blockIdx.y;
    int b  = blockIdx.z;
    int bh = b * NHc + h;

    const __half* Qb = d_Qh + (size_t)bh * Lc * HDc;
    const __half* Kb = d_Kh + (size_t)bh * Lc * HDc;
    const __half* Vt = d_Vt + (size_t)bh * HDc * Lc;
    __half* partp = d_parth + (size_t)chunk * (Bc*Lc*HIDc);

    __shared__ __align__(16) __half Ksh[TK3 * KSTH];   // [key][dim]
    __shared__ __align__(16) __half Vsh[HDc * VSTR];   // [dim(32)][key(32)]
    __shared__ __align__(16) __half psh[TQ3 * PSTR];   // [query][key] fp16

    int tid  = threadIdx.x;
    int w    = tid >> 5;
    int lane = tid & 31;
    int g    = lane >> 2;        // groupID
    int tig  = lane & 3;         // thread-in-group
    int qbase = w * 16;

    // Q A-fragments (fp16, k16 steps s=0,1), held in registers
    unsigned qa[2][4];
    const __half* Qp = Qb + (size_t)(l0 + qbase) * 32;
    #pragma unroll
    for (int s = 0; s < 2; ++s) {
        qa[s][0] = *(const unsigned*)(Qp + (size_t)g * 32 + 16*s + 2*tig);
        qa[s][1] = *(const unsigned*)(Qp + (size_t)(g + 8) * 32 + 16*s + 2*tig);
        qa[s][2] = *(const unsigned*)(Qp + (size_t)g * 32 + 16*s + 2*tig + 8);
        qa[s][3] = *(const unsigned*)(Qp + (size_t)(g + 8) * 32 + 16*s + 2*tig + 8);
    }

    int endA = 6 * ((l0 + qbase + g) / 6) + 6;        // causal end, row g
    int endB = 6 * ((l0 + qbase + g + 8) / 6) + 6;    // causal end, row g+8
    int wend = 6 * ((l0 + qbase + 15) / 6) + 6;       // warp's max end

    int kstart = chunk * CHUNK;
    int kend   = min(emax, kstart + CHUNK);           // CTA's chunk range

    float o[2][2][4] = {};       // O^T accum [md][nq][reg]
    float su_lo = 0.f, su_hi = 0.f;

    // tile loader mapping: 128 thr -> 32 rows x 8 halves each
    int trow = tid >> 2;
    int tcol = (tid & 3) * 8;

    uint4 kA = *(const uint4*)(Kb + (size_t)(kstart + trow) * 32 + tcol);
    uint4 vA = *(const uint4*)(Vt + (size_t)trow * Lc + kstart + tcol);

    for (int kb = kstart; kb < kend; kb += TK3) {
        __syncthreads();
        *(uint4*)(Ksh + trow * KSTH + tcol) = kA;
        *(uint4*)(Vsh + trow * VSTR + tcol) = vA;
        if (kb + TK3 < kend) {
            kA = *(const uint4*)(Kb + (size_t)(kb + TK3 + trow) * 32 + tcol);
            vA = *(const uint4*)(Vt + (size_t)trow * Lc + kb + TK3 + tcol);
        }
        __syncthreads();
        if (kb >= wend) continue;   // this warp done; still hits barriers

        // ---- scoring: S(16q x 32k) = Q * K^T via fp16 mma, per 8-key tile j ----
        #pragma unroll
        for (int j = 0; j < 4; ++j) {
            float c[4] = {0.f, 0.f, 0.f, 0.f};
            const __half* kr = Ksh + (8*j + g) * KSTH;
            #pragma unroll
            for (int s = 0; s < 2; ++s) {
                unsigned b0 = *(const unsigned*)(kr + 16*s + 2*tig);
                unsigned b1 = *(const unsigned*)(kr + 16*s + 2*tig + 8);
                mma_f16(c, qa[s][0], qa[s][1], qa[s][2], qa[s][3], b0, b1);
            }
            int ke = kb + 8*j + 2*tig;
            // p = 2^(s - 12) in fp16 pairs; causal mask by zeroing fp16 lanes
            unsigned pA = ex2_f16x2(c[0] - SHIFT2, c[1] - SHIFT2);
            unsigned pB = ex2_f16x2(c[2] - SHIFT2, c[3] - SHIFT2);
            unsigned mA = (ke < endA ? 0xFFFFu : 0u) | (ke + 1 < endA ? 0xFFFF0000u : 0u);
            unsigned mB = (ke < endB ? 0xFFFFu : 0u) | (ke + 1 < endB ? 0xFFFF0000u : 0u);
            pA &= mA;
            pB &= mB;
            float2 fA = __half22float2(*(__half2*)&pA);
            float2 fB = __half22float2(*(__half2*)&pB);
            su_lo += fA.x + fA.y;
            su_hi += fB.x + fB.y;
            *(unsigned*)(psh + (qbase + g) * PSTR + 8*j + 2*tig)     = pA;
            *(unsigned*)(psh + (qbase + g + 8) * PSTR + 8*j + 2*tig) = pB;
        }
        __syncwarp();

        // ---- PV: O^T(32d x 16q) += V^T * P^T via fp16 mma ----
        #pragma unroll
        for (int s = 0; s < 2; ++s) {
            unsigned pb00 = *(const unsigned*)(psh + (qbase + g) * PSTR + 16*s + 2*tig);
            unsigned pb01 = *(const unsigned*)(psh + (qbase + g) * PSTR + 16*s + 2*tig + 8);
            unsigned pb10 = *(const unsigned*)(psh + (qbase + 8 + g) * PSTR + 16*s + 2*tig);
            unsigned pb11 = *(const unsigned*)(psh + (qbase + 8 + g) * PSTR + 16*s + 2*tig + 8);
            #pragma unroll
            for (int md = 0; md < 2; ++md) {
                const __half* v0 = Vsh + (16*md + g) * VSTR;
                const __half* v1 = Vsh + (16*md + g + 8) * VSTR;
                unsigned a0 = *(const unsigned*)(v0 + 16*s + 2*tig);
                unsigned a1 = *(const unsigned*)(v1 + 16*s + 2*tig);
                unsigned a2 = *(const unsigned*)(v0 + 16*s + 2*tig + 8);
                unsigned a3 = *(const unsigned*)(v1 + 16*s + 2*tig + 8);
                mma_f16(o[md][0], a0, a1, a2, a3, pb00, pb01);
                mma_f16(o[md][1], a0, a1, a2, a3, pb10, pb11);
            }
        }
        __syncwarp();
    }

    // reduce denominator partials within each quad (over tig)
    su_lo += __shfl_xor_sync(0xffffffffu, su_lo, 1);
    su_lo += __shfl_xor_sync(0xffffffffu, su_lo, 2);
    su_hi += __shfl_xor_sync(0xffffffffu, su_hi, 1);
    su_hi += __shfl_xor_sync(0xffffffffu, su_hi, 2);
    if (tig == 0) {
        size_t sb = (size_t)chunk * (Bc*NHc*Lc) + (size_t)bh * Lc + l0 + qbase;
        d_psum[sb + g]     = su_lo;
        d_psum[sb + g + 8] = su_hi;
    }

    #pragma unroll
    for (int md = 0; md < 2; ++md) {
        #pragma unroll
        for (int nq = 0; nq < 2; ++nq) {
            int qloc = qbase + 8*nq + 2*tig;
            size_t base = ((size_t)b * Lc + l0 + qloc) * HIDc + h * HDc + 16*md + g;
            partp[base]            = __float2half_rn(o[md][nq][0]);
            partp[base + HIDc]     = __float2half_rn(o[md][nq][1]);
            partp[base + 8]        = __float2half_rn(o[md][nq][2]);
            partp[base + HIDc + 8] = __float2half_rn(o[md][nq][3]);
        }
    }
}

// ---------------------------------------------------------------------------
// Combine split-K partials + pool(6) -> d_SP.
// grid = Bc*Tt blocks x 128 threads; fully unrolled independent loads.
__global__ __launch_bounds__(128) void combine_kernel()
{
    int bt = blockIdx.x;
    int b = bt / Tt, tt = bt - b * Tt;
    int c = threadIdx.x;
    int h = c >> 5;

    int end = tt * Nf + Nf;
    int nc = (end + CHUNK - 1) / CHUNK;   // live chunks for this time block

    float p = 0.0f;
    #pragma unroll
    for (int k = 0; k < Nf; ++k) {
        int l = tt * Nf + k;
        float su = 0.f, oo = 0.f;
        #pragma unroll
        for (int cc = 0; cc < NCHUNK; ++cc) {
            if (cc < nc) {
                su += d_psum[(size_t)cc * (Bc*NHc*Lc) + ((size_t)b*NHc + h)*Lc + l];
                oo += __half2float(
                    d_parth[(size_t)cc * (Bc*Lc*HIDc) + ((size_t)b*Lc + l)*HIDc + c]);
            }
        }
        p += oo / su;
    }
    d_SP[(size_t)bt * HIDc + c] = p * (1.0f / Nf);
}

// ---------------------------------------------------------------------------
// o_w -> LN -> f_w -> SiLU on pooled rows.
// 2 rows per block, 512 blocks, 256 threads (dd reduction split in halves).
#define FTOK 2
__global__ __launch_bounds__(256) void final_kernel(
    const float* __restrict__ o_w,    const float* __restrict__ o_b,
    const float* __restrict__ f_ln_w, const float* __restrict__ f_ln_b,
    const float* __restrict__ f_w,    const float* __restrict__ f_b,
    float* __restrict__ out)
{
    int p0 = blockIdx.x * FTOK;
    int tid = threadIdx.x;
    int c = tid & 127;
    int half = tid >> 7;
    int w = c >> 5, lane = c & 31;
    int d0 = half * 64;

    __shared__ float sp[FTOK][128];
    __shared__ float pacc[2][FTOK][128];
    __shared__ float sln[FTOK][128];
    __shared__ float redA[FTOK][4], redB[FTOK][4];

    #pragma unroll
    for (int i = tid; i < FTOK * 128; i += 256)
        ((float*)sp)[i] = d_SP[(size_t)p0 * HIDc + i];
    __syncthreads();

    // ---- o_w matmul, dd split across halves (fully unrolled) ----
    float acc[FTOK] = {0.f, 0.f};
    #pragma unroll
    for (int dd = 0; dd < 64; ++dd) {
        float wv = o_w[(d0 + dd) * HIDc + c];
        #pragma unroll
        for (int t = 0; t < FTOK; ++t) acc[t] += sp[t][d0 + dd] * wv;
    }
    #pragma unroll
    for (int t = 0; t < FTOK; ++t) pacc[half][t][c] = acc[t];
    __syncthreads();

    float o[FTOK];
    #pragma unroll
    for (int t = 0; t < FTOK; ++t)
        o[t] = pacc[0][t][c] + pacc[1][t][c] + o_b[c];

    // ---- LayerNorm stats (half 0 only) ----
    if (half == 0) {
        #pragma unroll
        for (int t = 0; t < FTOK; ++t) {
            float s = o[t], s2 = o[t] * o[t];
            #pragma unroll
            for (int off = 16; off; off >>= 1) {
                s  += __shfl_xor_sync(0xffffffffu, s,  off);
                s2 += __shfl_xor_sync(0xffffffffu, s2, off);
            }
            if (lane == 0) { redA[t][w] = s; redB[t][w] = s2; }
        }
    }
    __syncthreads();
    if (half == 0) {
        #pragma unroll
        for (int t = 0; t < FTOK; ++t) {
            float S  = redA[t][0] + redA[t][1] + redA[t][2] + redA[t][3];
            float S2 = redB[t][0] + redB[t][1] + redB[t][2] + redB[t][3];
            float mu  = S * (1.0f / 128.0f);
            float var = S2 * (1.0f / 128.0f) - mu * mu;
            sln[t][c] = (o[t] - mu) * rsqrtf(var + EPSc) * f_ln_w[c] + f_ln_b[c];
        }
    }
    __syncthreads();

    // ---- f_w matmul, dd split across halves (fully unrolled) ----
    float f[FTOK] = {0.f, 0.f};
    #pragma unroll
    for (int dd = 0; dd < 64; ++dd) {
        float wv = f_w[(d0 + dd) * HIDc + c];
        #pragma unroll
        for (int t = 0; t < FTOK; ++t) f[t] += sln[t][d0 + dd] * wv;
    }
    #pragma unroll
    for (int t = 0; t < FTOK; ++t) pacc[half][t][c] = f[t];
    __syncthreads();

    if (half == 0) {
        #pragma unroll
        for (int t = 0; t < FTOK; ++t) {
            float ff = pacc[0][t][c] + pacc[1][t][c] + f_b[c];
            out[(size_t)(p0 + t) * FDc + c] = ff / (1.0f + __expf(-ff));
        }
    }
}

// ---------------------------------------------------------------------------
extern "C" void kernel_launch(void* const* d_in, const int* in_sizes, int n_in,
                              void* d_out, int out_size)
{
    const float* x      = (const float*)d_in[0];
    const float* g_ln_w = (const float*)d_in[1];
    const float* g_ln_b = (const float*)d_in[2];
    const float* g_w1   = (const float*)d_in[3];
    const float* g_b1   = (const float*)d_in[4];
    const float* g_w2   = (const float*)d_in[5];
    const float* g_b2   = (const float*)d_in[6];
    const float* q_w    = (const float*)d_in[7];
    const float* q_b    = (const float*)d_in[8];
    const float* k_w    = (const float*)d_in[9];
    const float* k_b    = (const float*)d_in[10];
    const float* v_w    = (const float*)d_in[11];
    const float* v_b    = (const float*)d_in[12];
    const float* o_w    = (const float*)d_in[13];
    const float* o_b    = (const float*)d_in[14];
    const float* f_ln_w = (const float*)d_in[15];
    const float* f_ln_b = (const float*)d_in[16];
    const float* f_w    = (const float*)d_in[17];
    const float* f_b    = (const float*)d_in[18];

    // exact CTA count for the (qtile, chunk) decomposition
    int total = 0;
    for (int bx = 0; bx < Lc / TQ3; ++bx) {
        int l0 = Lc - TQ3 * (bx + 1);
        int emax = 6 * ((l0 + TQ3 - 1) / 6) + 6;
        total += (emax + CHUNK - 1) / CHUNK;
    }

    qkv_gate_kernel<<<(Bc * Lc) / QTOK, 128>>>(x, g_ln_w, g_ln_b, g_w1, g_b1,
                                               g_w2, g_b2, q_w, q_b, k_w, k_b,
                                               v_w, v_b);
    attn_kernel<<<dim3(total, NHc, Bc), 128>>>();
    combine_kernel<<<Bc * Tt, 128>>>();
    final_kernel<<<(Bc * Tt) / FTOK, 256>>>(o_w, o_b, f_ln_w, f_ln_b, f_w, f_b,
                                            (float*)d_out);
}

// round 17
// speedup vs baseline: 1.2821x; 1.0138x over previous
#include <cuda_runtime.h>
#include <cuda_fp16.h>
#include <math.h>

// Problem constants
#define Bc   2
#define Tt   512
#define Nf   6
#define Dd   32
#define HIDc 128
#define NHc  4
#define HDc  32
#define Lc   3072      // Tt*Nf
#define GHc  32
#define FDc  128
#define EPSc 1e-5f

#define NCHUNK 6
#define CHUNK  512
#define SHIFT2 12.0f   // uniform log2-domain score shift (cancels in sum o / sum su)
#define LOG2E  1.4426950408889634f

// NOTE on the reference's max(softmax, 1e-9): masked-tail term contributes
// ~1e-9 * sum(V) ~ 3e-8 absolute (~3e-7 relative) and in-window probabilities
// are always >= ~2e-7 >> 1e-9, so the clamp is numerically invisible at the
// 1e-3 threshold. It is omitted.

// Scratch (device globals: no allocation allowed)
__device__ __half d_Qh[Bc*NHc*Lc*HDc];   // fp16 Q (pre-scaled by log2e/sqrt(HD)) [bh][l][d]
__device__ __half d_Kh[Bc*NHc*Lc*HDc];   // fp16 K [bh][l][d]
__device__ __half d_Vt[Bc*NHc*HDc*Lc];   // fp16 V transposed [bh][d][l]
__device__ __half d_parth[NCHUNK*Bc*Lc*HIDc]; // fp16 unnormalized attention partials
__device__ float  d_psum[NCHUNK*Bc*NHc*Lc];   // fp32 softmax denominator partials

// D(16x8) += A(16x16,f16) * B(16x8,f16), fp32 accum.
__device__ __forceinline__ void mma_f16(float c[4],
    unsigned a0, unsigned a1, unsigned a2, unsigned a3,
    unsigned b0, unsigned b1)
{
    asm volatile(
        "mma.sync.aligned.m16n8k16.row.col.f32.f16.f16.f32 "
        "{%0,%1,%2,%3}, {%4,%5,%6,%7}, {%8,%9}, {%0,%1,%2,%3};"
        : "+f"(c[0]), "+f"(c[1]), "+f"(c[2]), "+f"(c[3])
        : "r"(a0), "r"(a1), "r"(a2), "r"(a3), "r"(b0), "r"(b1));
}

// packed fp16 2^x
__device__ __forceinline__ unsigned ex2_f16x2(float x0, float x1) {
    unsigned in, out;
    asm("cvt.rn.f16x2.f32 %0, %2, %1;" : "=r"(in) : "f"(x0), "f"(x1));
    asm("ex2.approx.f16x2 %0, %1;" : "=r"(out) : "r"(in));
    return out;
}

// ---------------------------------------------------------------------------
// Fused gater + gated QKV. One block (128 threads) per 16 tokens.
#define QTOK 16
__global__ __launch_bounds__(128) void qkv_gate_kernel(const float* __restrict__ x,
    const float* __restrict__ g_ln_w, const float* __restrict__ g_ln_b,
    const float* __restrict__ g_w1,   const float* __restrict__ g_b1,
    const float* __restrict__ g_w2,   const float* __restrict__ g_b2,
    const float* __restrict__ q_w,    const float* __restrict__ q_b,
    const float* __restrict__ k_w,    const float* __restrict__ k_b,
    const float* __restrict__ v_w,    const float* __restrict__ v_b)
{
    const float SC = 0.17677669529663688f * LOG2E;  // log2e/sqrt(32)
    int t0 = blockIdx.x * QTOK;
    int tid = threadIdx.x;
    int w = tid >> 5, lane = tid & 31;

    __shared__ float xs[QTOK][32];
    __shared__ float xns[QTOK][32];
    __shared__ float gate[QTOK];

    #pragma unroll
    for (int i = tid; i < QTOK*32; i += 128)
        xs[i >> 5][i & 31] = x[(size_t)t0 * 32 + i];
    __syncthreads();

    // LayerNorm for gater input (warp w: tokens 4w..4w+3)
    #pragma unroll
    for (int kk = 0; kk < 4; ++kk) {
        int t = w * 4 + kk;
        float xv = xs[t][lane];
        float s = xv, s2 = xv * xv;
        #pragma unroll
        for (int o = 16; o; o >>= 1) {
            s  += __shfl_xor_sync(0xffffffffu, s,  o);
            s2 += __shfl_xor_sync(0xffffffffu, s2, o);
        }
        float mu  = s * (1.0f / 32.0f);
        float var = s2 * (1.0f / 32.0f) - mu * mu;
        xns[t][lane] = (xv - mu) * rsqrtf(var + EPSc) * g_ln_w[lane] + g_ln_b[lane];
    }
    __syncthreads();

    // gater MLP (smem-broadcast matmul)
    #pragma unroll
    for (int kk = 0; kk < 4; ++kk) {
        int t = w * 4 + kk;
        float h = g_b1[lane];
        #pragma unroll
        for (int d = 0; d < 32; ++d)
            h += xns[t][d] * g_w1[d * GHc + lane];
        h = h / (1.0f + __expf(-h));
        float gp = h * g_w2[lane];
        #pragma unroll
        for (int o = 16; o; o >>= 1) gp += __shfl_xor_sync(0xffffffffu, gp, o);
        if (lane == 0) gate[t] = 1.0f / (1.0f + __expf(-(gp + g_b2[0])));
    }
    __syncthreads();

    int c = tid;
    float q[QTOK], k[QTOK], v[QTOK];
    float qb = q_b[c], kb = k_b[c], vb = v_b[c];
    #pragma unroll
    for (int t = 0; t < QTOK; ++t) { q[t] = qb; k[t] = kb; v[t] = vb; }
    #pragma unroll
    for (int dd = 0; dd < 32; ++dd) {
        float wq = q_w[dd * HIDc + c];
        float wk = k_w[dd * HIDc + c];
        float wv = v_w[dd * HIDc + c];
        #pragma unroll
        for (int t = 0; t < QTOK; ++t) {
            float xd = xs[t][dd];
            q[t] += xd * wq; k[t] += xd * wk; v[t] += xd * wv;
        }
    }

    int hh = c >> 5, d2 = c & 31;
    int b = t0 / Lc, lbase = t0 - b * Lc;
    int bh = b * NHc + hh;

    union { __half h[QTOK]; uint4 u[2]; } vp;
    #pragma unroll
    for (int t = 0; t < QTOK; ++t) {
        float g = gate[t];
        size_t idx = ((size_t)bh * Lc + lbase + t) * HDc + d2;
        d_Qh[idx] = __float2half_rn(q[t] * g * SC);
        d_Kh[idx] = __float2half_rn(k[t] * g);
        vp.h[t]   = __float2half_rn(v[t] * g);
    }
    uint4* vdst = (uint4*)&d_Vt[((size_t)bh * HDc + d2) * Lc + lbase];
    vdst[0] = vp.u[0];
    vdst[1] = vp.u[1];
}

// ---------------------------------------------------------------------------
// Tensor-core block-causal attention: fp16 scoring + fp16 PV (fp32 accum),
// split-K over 512-key chunks; scores in log2 domain, p = 2^(s - 12) via
// ex2.approx.f16x2 (shift cancels in sum o / sum su).
// 128 threads, 4 warps x 16 queries = 64 queries/CTA, 32-key tiles.
#define TQ3 64
#define TK3 32
#define KSTH 40  // K smem row stride (halves)
#define VSTR 40  // V^T smem row stride (halves)
#define PSTR 40  // psh row stride (halves)
__global__ __launch_bounds__(128, 7) void attn_kernel()
{
    // map blockIdx.x -> (qtile bx, key chunk)
    int id = blockIdx.x;
    int bx = 0, l0, emax;
    for (;;) {
        l0 = Lc - TQ3 * (bx + 1);
        emax = 6 * ((l0 + TQ3 - 1) / 6) + 6;
        int nch = (emax + CHUNK - 1) / CHUNK;
        if (id < nch) break;
        id -= nch; ++bx;
    }
    int chunk = id;
    int h  = blockIdx.y;
    int b  = blockIdx.z;
    int bh = b * NHc + h;

    const __half* Qb = d_Qh + (size_t)bh * Lc * HDc;
    const __half* Kb = d_Kh + (size_t)bh * Lc * HDc;
    const __half* Vt = d_Vt + (size_t)bh * HDc * Lc;
    __half* partp = d_parth + (size_t)chunk * (Bc*Lc*HIDc);

    __shared__ __align__(16) __half Ksh[TK3 * KSTH];   // [key][dim]
    __shared__ __align__(16) __half Vsh[HDc * VSTR];   // [dim(32)][key(32)]
    __shared__ __align__(16) __half psh[TQ3 * PSTR];   // [query][key] fp16

    int tid  = threadIdx.x;
    int w    = tid >> 5;
    int lane = tid & 31;
    int g    = lane >> 2;        // groupID
    int tig  = lane & 3;         // thread-in-group
    int qbase = w * 16;

    // Q A-fragments (fp16, k16 steps s=0,1), held in registers
    unsigned qa[2][4];
    const __half* Qp = Qb + (size_t)(l0 + qbase) * 32;
    #pragma unroll
    for (int s = 0; s < 2; ++s) {
        qa[s][0] = *(const unsigned*)(Qp + (size_t)g * 32 + 16*s + 2*tig);
        qa[s][1] = *(const unsigned*)(Qp + (size_t)(g + 8) * 32 + 16*s + 2*tig);
        qa[s][2] = *(const unsigned*)(Qp + (size_t)g * 32 + 16*s + 2*tig + 8);
        qa[s][3] = *(const unsigned*)(Qp + (size_t)(g + 8) * 32 + 16*s + 2*tig + 8);
    }

    int endA = 6 * ((l0 + qbase + g) / 6) + 6;        // causal end, row g
    int endB = 6 * ((l0 + qbase + g + 8) / 6) + 6;    // causal end, row g+8
    int wend = 6 * ((l0 + qbase + 15) / 6) + 6;       // warp's max end

    int kstart = chunk * CHUNK;
    int kend   = min(emax, kstart + CHUNK);           // CTA's chunk range

    float o[2][2][4] = {};       // O^T accum [md][nq][reg]
    float su_lo = 0.f, su_hi = 0.f;

    // tile loader mapping: 128 thr -> 32 rows x 8 halves each
    int trow = tid >> 2;
    int tcol = (tid & 3) * 8;

    uint4 kA = *(const uint4*)(Kb + (size_t)(kstart + trow) * 32 + tcol);
    uint4 vA = *(const uint4*)(Vt + (size_t)trow * Lc + kstart + tcol);

    for (int kb = kstart; kb < kend; kb += TK3) {
        __syncthreads();
        *(uint4*)(Ksh + trow * KSTH + tcol) = kA;
        *(uint4*)(Vsh + trow * VSTR + tcol) = vA;
        if (kb + TK3 < kend) {
            kA = *(const uint4*)(Kb + (size_t)(kb + TK3 + trow) * 32 + tcol);
            vA = *(const uint4*)(Vt + (size_t)trow * Lc + kb + TK3 + tcol);
        }
        __syncthreads();
        if (kb >= wend) continue;   // this warp done; still hits barriers

        // ---- scoring: S(16q x 32k) = Q * K^T via fp16 mma, per 8-key tile j ----
        #pragma unroll
        for (int j = 0; j < 4; ++j) {
            float c[4] = {0.f, 0.f, 0.f, 0.f};
            const __half* kr = Ksh + (8*j + g) * KSTH;
            #pragma unroll
            for (int s = 0; s < 2; ++s) {
                unsigned b0 = *(const unsigned*)(kr + 16*s + 2*tig);
                unsigned b1 = *(const unsigned*)(kr + 16*s + 2*tig + 8);
                mma_f16(c, qa[s][0], qa[s][1], qa[s][2], qa[s][3], b0, b1);
            }
            int ke = kb + 8*j + 2*tig;
            // p = 2^(s - 12) in fp16 pairs; causal mask by zeroing fp16 lanes
            unsigned pA = ex2_f16x2(c[0] - SHIFT2, c[1] - SHIFT2);
            unsigned pB = ex2_f16x2(c[2] - SHIFT2, c[3] - SHIFT2);
            unsigned mA = (ke < endA ? 0xFFFFu : 0u) | (ke + 1 < endA ? 0xFFFF0000u : 0u);
            unsigned mB = (ke < endB ? 0xFFFFu : 0u) | (ke + 1 < endB ? 0xFFFF0000u : 0u);
            pA &= mA;
            pB &= mB;
            float2 fA = __half22float2(*(__half2*)&pA);
            float2 fB = __half22float2(*(__half2*)&pB);
            su_lo += fA.x + fA.y;
            su_hi += fB.x + fB.y;
            *(unsigned*)(psh + (qbase + g) * PSTR + 8*j + 2*tig)     = pA;
            *(unsigned*)(psh + (qbase + g + 8) * PSTR + 8*j + 2*tig) = pB;
        }
        __syncwarp();

        // ---- PV: O^T(32d x 16q) += V^T * P^T via fp16 mma ----
        #pragma unroll
        for (int s = 0; s < 2; ++s) {
            unsigned pb00 = *(const unsigned*)(psh + (qbase + g) * PSTR + 16*s + 2*tig);
            unsigned pb01 = *(const unsigned*)(psh + (qbase + g) * PSTR + 16*s + 2*tig + 8);
            unsigned pb10 = *(const unsigned*)(psh + (qbase + 8 + g) * PSTR + 16*s + 2*tig);
            unsigned pb11 = *(const unsigned*)(psh + (qbase + 8 + g) * PSTR + 16*s + 2*tig + 8);
            #pragma unroll
            for (int md = 0; md < 2; ++md) {
                const __half* v0 = Vsh + (16*md + g) * VSTR;
                const __half* v1 = Vsh + (16*md + g + 8) * VSTR;
                unsigned a0 = *(const unsigned*)(v0 + 16*s + 2*tig);
                unsigned a1 = *(const unsigned*)(v1 + 16*s + 2*tig);
                unsigned a2 = *(const unsigned*)(v0 + 16*s + 2*tig + 8);
                unsigned a3 = *(const unsigned*)(v1 + 16*s + 2*tig + 8);
                mma_f16(o[md][0], a0, a1, a2, a3, pb00, pb01);
                mma_f16(o[md][1], a0, a1, a2, a3, pb10, pb11);
            }
        }
        __syncwarp();
    }

    // reduce denominator partials within each quad (over tig)
    su_lo += __shfl_xor_sync(0xffffffffu, su_lo, 1);
    su_lo += __shfl_xor_sync(0xffffffffu, su_lo, 2);
    su_hi += __shfl_xor_sync(0xffffffffu, su_hi, 1);
    su_hi += __shfl_xor_sync(0xffffffffu, su_hi, 2);
    if (tig == 0) {
        size_t sb = (size_t)chunk * (Bc*NHc*Lc) + (size_t)bh * Lc + l0 + qbase;
        d_psum[sb + g]     = su_lo;
        d_psum[sb + g + 8] = su_hi;
    }

    #pragma unroll
    for (int md = 0; md < 2; ++md) {
        #pragma unroll
        for (int nq = 0; nq < 2; ++nq) {
            int qloc = qbase + 8*nq + 2*tig;
            size_t base = ((size_t)b * Lc + l0 + qloc) * HIDc + h * HDc + 16*md + g;
            partp[base]            = __float2half_rn(o[md][nq][0]);
            partp[base + HIDc]     = __float2half_rn(o[md][nq][1]);
            partp[base + 8]        = __float2half_rn(o[md][nq][2]);
            partp[base + HIDc + 8] = __float2half_rn(o[md][nq][3]);
        }
    }
}

// ---------------------------------------------------------------------------
// Fused combine + pool(6) + o_w -> LN -> f_w -> SiLU.
// 2 rows per block, 512 blocks, 256 threads. Each 128-thread half performs
// the full split-K combine for ONE row (same total parallelism as the old
// standalone combine kernel), then the two halves split the dd reduction.
#define FTOK 2
__global__ __launch_bounds__(256) void final_kernel(
    const float* __restrict__ o_w,    const float* __restrict__ o_b,
    const float* __restrict__ f_ln_w, const float* __restrict__ f_ln_b,
    const float* __restrict__ f_w,    const float* __restrict__ f_b,
    float* __restrict__ out)
{
    int p0 = blockIdx.x * FTOK;
    int tid = threadIdx.x;
    int c = tid & 127;
    int half = tid >> 7;
    int w = c >> 5, lane = c & 31;
    int d0 = half * 64;

    __shared__ float sp[FTOK][128];
    __shared__ float pacc[2][FTOK][128];
    __shared__ float sln[FTOK][128];
    __shared__ float redA[FTOK][4], redB[FTOK][4];

    // ---- combine split-K partials + pool for row (p0 + half) ----
    {
        int bt = p0 + half;
        int b = bt / Tt, tt = bt - b * Tt;
        int head = c >> 5;
        int end = tt * Nf + Nf;
        int nc = (end + CHUNK - 1) / CHUNK;
        float p = 0.0f;
        #pragma unroll
        for (int k = 0; k < Nf; ++k) {
            int l = tt * Nf + k;
            float su = 0.f, oo = 0.f;
            #pragma unroll
            for (int cc = 0; cc < NCHUNK; ++cc) {
                if (cc < nc) {
                    su += d_psum[(size_t)cc * (Bc*NHc*Lc) + ((size_t)b*NHc + head)*Lc + l];
                    oo += __half2float(
                        d_parth[(size_t)cc * (Bc*Lc*HIDc) + ((size_t)b*Lc + l)*HIDc + c]);
                }
            }
            p += oo / su;
        }
        sp[half][c] = p * (1.0f / Nf);
    }
    __syncthreads();

    // ---- o_w matmul, dd split across halves, 4-way ILP ----
    float a4[FTOK][4] = {};
    #pragma unroll
    for (int dd = 0; dd < 64; dd += 4) {
        #pragma unroll
        for (int j = 0; j < 4; ++j) {
            float wv = o_w[(d0 + dd + j) * HIDc + c];
            #pragma unroll
            for (int t = 0; t < FTOK; ++t)
                a4[t][j] += sp[t][d0 + dd + j] * wv;
        }
    }
    #pragma unroll
    for (int t = 0; t < FTOK; ++t)
        pacc[half][t][c] = (a4[t][0] + a4[t][1]) + (a4[t][2] + a4[t][3]);
    __syncthreads();

    float o[FTOK];
    #pragma unroll
    for (int t = 0; t < FTOK; ++t)
        o[t] = pacc[0][t][c] + pacc[1][t][c] + o_b[c];

    // ---- LayerNorm stats (half 0 only) ----
    if (half == 0) {
        #pragma unroll
        for (int t = 0; t < FTOK; ++t) {
            float s = o[t], s2 = o[t] * o[t];
            #pragma unroll
            for (int off = 16; off; off >>= 1) {
                s  += __shfl_xor_sync(0xffffffffu, s,  off);
                s2 += __shfl_xor_sync(0xffffffffu, s2, off);
            }
            if (lane == 0) { redA[t][w] = s; redB[t][w] = s2; }
        }
    }
    __syncthreads();
    if (half == 0) {
        #pragma unroll
        for (int t = 0; t < FTOK; ++t) {
            float S  = redA[t][0] + redA[t][1] + redA[t][2] + redA[t][3];
            float S2 = redB[t][0] + redB[t][1] + redB[t][2] + redB[t][3];
            float mu  = S * (1.0f / 128.0f);
            float var = S2 * (1.0f / 128.0f) - mu * mu;
            sln[t][c] = (o[t] - mu) * rsqrtf(var + EPSc) * f_ln_w[c] + f_ln_b[c];
        }
    }
    __syncthreads();

    // ---- f_w matmul, dd split across halves, 4-way ILP ----
    float f4[FTOK][4] = {};
    #pragma unroll
    for (int dd = 0; dd < 64; dd += 4) {
        #pragma unroll
        for (int j = 0; j < 4; ++j) {
            float wv = f_w[(d0 + dd + j) * HIDc + c];
            #pragma unroll
            for (int t = 0; t < FTOK; ++t)
                f4[t][j] += sln[t][d0 + dd + j] * wv;
        }
    }
    #pragma unroll
    for (int t = 0; t < FTOK; ++t)
        pacc[half][t][c] = (f4[t][0] + f4[t][1]) + (f4[t][2] + f4[t][3]);
    __syncthreads();

    if (half == 0) {
        #pragma unroll
        for (int t = 0; t < FTOK; ++t) {
            float ff = pacc[0][t][c] + pacc[1][t][c] + f_b[c];
            out[(size_t)(p0 + t) * FDc + c] = ff / (1.0f + __expf(-ff));
        }
    }
}

// ---------------------------------------------------------------------------
extern "C" void kernel_launch(void* const* d_in, const int* in_sizes, int n_in,
                              void* d_out, int out_size)
{
    const float* x      = (const float*)d_in[0];
    const float* g_ln_w = (const float*)d_in[1];
    const float* g_ln_b = (const float*)d_in[2];
    const float* g_w1   = (const float*)d_in[3];
    const float* g_b1   = (const float*)d_in[4];
    const float* g_w2   = (const float*)d_in[5];
    const float* g_b2   = (const float*)d_in[6];
    const float* q_w    = (const float*)d_in[7];
    const float* q_b    = (const float*)d_in[8];
    const float* k_w    = (const float*)d_in[9];
    const float* k_b    = (const float*)d_in[10];
    const float* v_w    = (const float*)d_in[11];
    const float* v_b    = (const float*)d_in[12];
    const float* o_w    = (const float*)d_in[13];
    const float* o_b    = (const float*)d_in[14];
    const float* f_ln_w = (const float*)d_in[15];
    const float* f_ln_b = (const float*)d_in[16];
    const float* f_w    = (const float*)d_in[17];
    const float* f_b    = (const float*)d_in[18];

    // exact CTA count for the (qtile, chunk) decomposition
    int total = 0;
    for (int bx = 0; bx < Lc / TQ3; ++bx) {
        int l0 = Lc - TQ3 * (bx + 1);
        int emax = 6 * ((l0 + TQ3 - 1) / 6) + 6;
        total += (emax + CHUNK - 1) / CHUNK;
    }

    qkv_gate_kernel<<<(Bc * Lc) / QTOK, 128>>>(x, g_ln_w, g_ln_b, g_w1, g_b1,
                                               g_w2, g_b2, q_w, q_b, k_w, k_b,
                                               v_w, v_b);
    attn_kernel<<<dim3(total, NHc, Bc), 128>>>();
    final_kernel<<<(Bc * Tt) / FTOK, 256>>>(o_w, o_b, f_ln_w, f_ln_b, f_w, f_b,
                                            (float*)d_out);
}